// round 7
// baseline (speedup 1.0000x reference)
#include <cuda_runtime.h>

#define NN 50000
#define NE 500000
#define D 128
#define TDIM 32
#define EDIM 160
#define TE 128       // edges per block (edge kernel)
#define SA 164       // attr tile smem stride (words)
#define SE 132       // e-result smem stride (words)
#define SX 132       // x tile smem stride (words, proj mma)

// ---- scratch (no cudaMalloc allowed) ----
__device__ float g_q[NN * D];
__device__ float g_k[NN * D];
__device__ float g_v[NN * D];
__device__ float g_agg[NN * D];
__device__ float g_sum[NN * 2];
__device__ unsigned g_we_sw[EDIM * D];     // pre-swizzled tf32 We
__device__ unsigned g_w_sw[4 * D * D];     // pre-swizzled tf32 Wq|Wk|Wv|Wskip
__device__ int   g_idx64;

// ---- helpers ----
__device__ __forceinline__ unsigned to_tf32(float f) {
    unsigned r;
    asm("cvt.rna.tf32.f32 %0, %1;" : "=r"(r) : "f"(f));
    return r;
}
__device__ __forceinline__ void red_v4(float* p, float a, float b, float c, float d) {
    asm volatile("red.global.add.v4.f32 [%0], {%1,%2,%3,%4};"
                 :: "l"(p), "f"(a), "f"(b), "f"(c), "f"(d) : "memory");
}
__device__ __forceinline__ void red_1(float* p, float a) {
    asm volatile("red.global.add.f32 [%0], %1;" :: "l"(p), "f"(a) : "memory");
}
__device__ __forceinline__ void mma_tf32(float* c, const unsigned* a,
                                         unsigned b0, unsigned b1) {
    asm volatile(
        "mma.sync.aligned.m16n8k8.row.col.f32.tf32.tf32.f32 "
        "{%0,%1,%2,%3}, {%4,%5,%6,%7}, {%8,%9}, {%0,%1,%2,%3};"
        : "+f"(c[0]), "+f"(c[1]), "+f"(c[2]), "+f"(c[3])
        : "r"(a[0]), "r"(a[1]), "r"(a[2]), "r"(a[3]), "r"(b0), "r"(b1));
}

// Detect int64 vs int32 edge_index.
__global__ void detect_kernel(const long long* __restrict__ ei) {
    if (threadIdx.x == 0 && blockIdx.x == 0) {
        bool ok = true;
        #pragma unroll
        for (int i = 0; i < 16; i++) {
            long long v = ei[i];
            if (v < 0 || v >= NN) ok = false;
        }
        g_idx64 = ok ? 1 : 0;
    }
}

// Pre-swizzle We into tf32: within each 64-col half, col (ni*8+g) -> (g*8+ni).
__global__ void swizzle_we_kernel(const float* __restrict__ We) {
    int i = blockIdx.x * blockDim.x + threadIdx.x;
    if (i < EDIM * D) {
        const int k = i >> 7, c = i & 127;
        const int half = c >> 6, rem = c & 63;
        const int ni = rem >> 3, g = rem & 7;
        g_we_sw[k * D + half * 64 + g * 8 + ni] = to_tf32(__ldg(We + i));
    }
}

// Pre-swizzle the four node-projection weights.
__global__ void swizzle_w_kernel(const float* __restrict__ Wq,
                                 const float* __restrict__ Wk,
                                 const float* __restrict__ Wv,
                                 const float* __restrict__ Ws) {
    int i = blockIdx.x * blockDim.x + threadIdx.x;
    if (i < 4 * D * D) {
        const int mat = i >> 14, rem = i & 16383;
        const int k = rem >> 7, c = rem & 127;
        const int half = c >> 6, r2 = c & 63;
        const int ni = r2 >> 3, g = r2 & 7;
        const float* W = (mat == 0) ? Wq : (mat == 1) ? Wk : (mat == 2) ? Wv : Ws;
        g_w_sw[mat * D * D + k * D + half * 64 + g * 8 + ni] = to_tf32(__ldg(W + rem));
    }
}

__global__ void zero_kernel() {
    int idx = blockIdx.x * blockDim.x + threadIdx.x;
    if (idx < NN * D) g_agg[idx] = 0.0f;
    if (idx < NN * 2) g_sum[idx] = 0.0f;
}

// ---- proj (tf32 mma): q,k,v,skip = x @ W + b. grid = (nodeTiles, 4 mats) ----
__global__ __launch_bounds__(256, 2) void proj_kernel(
    const float* __restrict__ x,
    const float* __restrict__ bq, const float* __restrict__ bk,
    const float* __restrict__ bv, const float* __restrict__ bs,
    float* __restrict__ out)
{
    extern __shared__ unsigned sX[];   // [128][SX] tf32 x tile (67.6KB)
    const int tid = threadIdx.x;
    const int n0  = blockIdx.x * 128;
    const int mat = blockIdx.y;

    for (int i = tid; i < 128 * 32; i += 256) {
        const int n = i >> 5, q = i & 31;
        float4 m = make_float4(0, 0, 0, 0);
        if (n0 + n < NN) m = __ldg((const float4*)(x + (size_t)(n0 + n) * D) + q);
        unsigned* p = sX + n * SX + 4 * q;
        p[0] = to_tf32(m.x); p[1] = to_tf32(m.y);
        p[2] = to_tf32(m.z); p[3] = to_tf32(m.w);
    }
    __syncthreads();

    const int wid = tid >> 5, lane = tid & 31;
    const int g = lane >> 2, tg = lane & 3;
    const int wm = wid & 3, wn = wid >> 2;

    float acc[2][8][4];
    #pragma unroll
    for (int mi = 0; mi < 2; mi++)
        #pragma unroll
        for (int ni = 0; ni < 8; ni++)
            #pragma unroll
            for (int r = 0; r < 4; r++) acc[mi][ni][r] = 0.f;

    const unsigned* Abase = sX + (wm * 32 + g) * SX + tg;
    const unsigned* Bb    = g_w_sw + mat * D * D + wn * 64 + g * 8;

    #pragma unroll 2
    for (int ks = 0; ks < D / 8; ks++) {
        const int k0 = ks * 8;
        unsigned a[2][4];
        #pragma unroll
        for (int mi = 0; mi < 2; mi++) {
            const unsigned* ap = Abase + mi * 16 * SX + k0;
            a[mi][0] = ap[0];
            a[mi][1] = ap[8 * SX];
            a[mi][2] = ap[4];
            a[mi][3] = ap[8 * SX + 4];
        }
        const uint4* p0 = (const uint4*)(Bb + (k0 + tg) * D);
        const uint4* p1 = (const uint4*)(Bb + (k0 + tg + 4) * D);
        const uint4 b0lo = __ldg(p0), b0hi = __ldg(p0 + 1);
        const uint4 b1lo = __ldg(p1), b1hi = __ldg(p1 + 1);
        const unsigned b0[8] = {b0lo.x, b0lo.y, b0lo.z, b0lo.w,
                                b0hi.x, b0hi.y, b0hi.z, b0hi.w};
        const unsigned b1[8] = {b1lo.x, b1lo.y, b1lo.z, b1lo.w,
                                b1hi.x, b1hi.y, b1hi.z, b1hi.w};
        #pragma unroll
        for (int ni = 0; ni < 8; ni++) {
            mma_tf32(acc[0][ni], a[0], b0[ni], b1[ni]);
            mma_tf32(acc[1][ni], a[1], b0[ni], b1[ni]);
        }
    }

    const float* bias = (mat == 0) ? bq : (mat == 1) ? bk : (mat == 2) ? bv : bs;
    float* dst = (mat == 0) ? g_q : (mat == 1) ? g_k : (mat == 2) ? g_v : out;

    #pragma unroll
    for (int mi = 0; mi < 2; mi++) {
        const int r0 = n0 + wm * 32 + mi * 16 + g;
        #pragma unroll
        for (int ni = 0; ni < 8; ni++) {
            const int c = wn * 64 + ni * 8 + 2 * tg;
            const float2 bb = __ldg((const float2*)(bias + c));
            if (r0 < NN)
                *(float2*)(dst + (size_t)r0 * D + c) =
                    make_float2(acc[mi][ni][0] + bb.x, acc[mi][ni][1] + bb.y);
            if (r0 + 8 < NN)
                *(float2*)(dst + (size_t)(r0 + 8) * D + c) =
                    make_float2(acc[mi][ni][2] + bb.x, acc[mi][ni][3] + bb.y);
        }
    }
}

// ---- edge (fused): attr build + tf32 GEMM + attention epilogue ----
__global__ __launch_bounds__(256, 2) void edge_kernel(
    const void*  __restrict__ ei_raw,
    const float* __restrict__ last_update,
    const float* __restrict__ t,
    const float* __restrict__ msg,
    const float* __restrict__ time_w,
    const float* __restrict__ time_b)
{
    extern __shared__ unsigned sA[];    // [TE][SA] tf32 attr tile (84KB)
    float* eS = (float*)sA;             // [TE][SE] e-result, overlays sA post-GEMM
    __shared__ int   s_src[TE], s_dst[TE];
    __shared__ float s_rel[TE];

    const int tid = threadIdx.x;
    const int e0  = blockIdx.x * TE;

    // phase 1: indices + rel time
    if (tid < TE) {
        const int eg = e0 + tid;
        int src = 0, dst = 0; float rel = 0.f;
        if (eg < NE) {
            if (g_idx64) {
                const long long* p = (const long long*)ei_raw;
                src = (int)__ldg(p + eg); dst = (int)__ldg(p + NE + eg);
            } else {
                const int* p = (const int*)ei_raw;
                src = __ldg(p + eg); dst = __ldg(p + NE + eg);
            }
            rel = __ldg(last_update + src) - __ldg(t + eg);
        }
        s_src[tid] = src; s_dst[tid] = dst; s_rel[tid] = rel;
    }
    __syncthreads();

    // phase 2: build attr tile (tf32)
    for (int i = tid; i < TE * TDIM; i += 256) {          // time-encode cols [0,32)
        const int e = i >> 5, k = i & 31;
        float v = 0.f;
        if (e0 + e < NE)
            v = cosf(s_rel[e] * __ldg(time_w + k) + __ldg(time_b + k));
        sA[e * SA + k] = to_tf32(v);
    }
    for (int i = tid; i < TE * 32; i += 256) {            // msg cols [32,160)
        const int e = i >> 5, q = i & 31;
        float4 m = make_float4(0, 0, 0, 0);
        if (e0 + e < NE) m = __ldg((const float4*)(msg + (size_t)(e0 + e) * D) + q);
        unsigned* p = sA + e * SA + TDIM + 4 * q;
        p[0] = to_tf32(m.x); p[1] = to_tf32(m.y);
        p[2] = to_tf32(m.z); p[3] = to_tf32(m.w);
    }
    __syncthreads();

    // phase 3: GEMM. 8 warps: 4(M) x 2(N); warp tile 32x64.
    const int wid = tid >> 5, lane = tid & 31;
    const int g = lane >> 2, tg = lane & 3;
    const int wm = wid & 3, wn = wid >> 2;

    float acc[2][8][4];
    #pragma unroll
    for (int mi = 0; mi < 2; mi++)
        #pragma unroll
        for (int ni = 0; ni < 8; ni++)
            #pragma unroll
            for (int r = 0; r < 4; r++) acc[mi][ni][r] = 0.f;

    const unsigned* Abase = sA + (wm * 32 + g) * SA + tg;
    const unsigned* Bb    = g_we_sw + wn * 64 + g * 8;

    #pragma unroll 2
    for (int ks = 0; ks < EDIM / 8; ks++) {
        const int k0 = ks * 8;
        unsigned a[2][4];
        #pragma unroll
        for (int mi = 0; mi < 2; mi++) {
            const unsigned* ap = Abase + mi * 16 * SA + k0;
            a[mi][0] = ap[0];
            a[mi][1] = ap[8 * SA];
            a[mi][2] = ap[4];
            a[mi][3] = ap[8 * SA + 4];
        }
        const uint4* p0 = (const uint4*)(Bb + (k0 + tg) * D);
        const uint4* p1 = (const uint4*)(Bb + (k0 + tg + 4) * D);
        const uint4 b0lo = __ldg(p0), b0hi = __ldg(p0 + 1);
        const uint4 b1lo = __ldg(p1), b1hi = __ldg(p1 + 1);
        const unsigned b0[8] = {b0lo.x, b0lo.y, b0lo.z, b0lo.w,
                                b0hi.x, b0hi.y, b0hi.z, b0hi.w};
        const unsigned b1[8] = {b1lo.x, b1lo.y, b1lo.z, b1lo.w,
                                b1hi.x, b1hi.y, b1hi.z, b1hi.w};
        #pragma unroll
        for (int ni = 0; ni < 8; ni++) {
            mma_tf32(acc[0][ni], a[0], b0[ni], b1[ni]);
            mma_tf32(acc[1][ni], a[1], b0[ni], b1[ni]);
        }
    }
    __syncthreads();   // all warps done reading sA

    // phase 4: accumulators -> smem e-matrix (note N-swizzle: col g*8+ni)
    #pragma unroll
    for (int mi = 0; mi < 2; mi++) {
        const int r0 = wm * 32 + mi * 16 + g;
        #pragma unroll
        for (int ni = 0; ni < 8; ni++) {
            const int c = wn * 64 + (g * 8 + ni & 0) * 0;   // placeholder, fixed below
            (void)c;
        }
    }
    // The B pre-swizzle maps logical col (ni*8+gg) to storage (gg*8+ni) within a
    // 64-half; an mma with b at storage slot s=g*8+ni computes logical col
    // c = ni*8 + g ... inverse: for accumulator [ni] of thread-group g the
    // LOGICAL column is wn*64 + ni*8 + 2*tg? No: B fragment lane mapping uses
    // storage (g*8+ni) -> logical (ni*8+g) was the swizzle; mma's n-index for
    // accumulator c-frag is (what the B fragment represented) = logical col.
    // acc[mi][ni] regs {0,1}: logical cols (ni*8+g_col_pair) per standard
    // m16n8k8 layout: col = n0 + 2*tg + {0,1}, n-tile = storage slot ni -> the
    // n-tile's logical base is the swizzled origin. Since the same swizzle was
    // validated in rounds 5-6 writing to column c = wn*64 + ni*8 + 2*tg, reuse it:
    #pragma unroll
    for (int mi = 0; mi < 2; mi++) {
        const int r0 = wm * 32 + mi * 16 + g;
        #pragma unroll
        for (int ni = 0; ni < 8; ni++) {
            const int c = wn * 64 + ni * 8 + 2 * tg;
            *(float2*)&eS[r0 * SE + c]       = make_float2(acc[mi][ni][0], acc[mi][ni][1]);
            *(float2*)&eS[(r0 + 8) * SE + c] = make_float2(acc[mi][ni][2], acc[mi][ni][3]);
        }
    }
    __syncthreads();

    // phase 5: attention epilogue. Warp handles 16 edges; lane owns 4 cols.
    const int col = lane * 4;
    #pragma unroll 4
    for (int ii = 0; ii < 16; ii++) {
        const int eL = wid * 16 + ii;
        const int eg = e0 + eL;
        if (eg < NE) {
            const int src = s_src[eL], dst = s_dst[eL];
            const float4 ev = *(const float4*)&eS[eL * SE + col];
            const float4 qi = *(const float4*)(g_q + (size_t)dst * D + col);
            float4 kj = *(const float4*)(g_k + (size_t)src * D + col);
            float4 vj = *(const float4*)(g_v + (size_t)src * D + col);
            kj.x += ev.x; kj.y += ev.y; kj.z += ev.z; kj.w += ev.w;
            vj.x += ev.x; vj.y += ev.y; vj.z += ev.z; vj.w += ev.w;

            float p = qi.x * kj.x + qi.y * kj.y + qi.z * kj.z + qi.w * kj.w;
            p += __shfl_xor_sync(0xffffffffu, p, 1);
            p += __shfl_xor_sync(0xffffffffu, p, 2);
            p += __shfl_xor_sync(0xffffffffu, p, 4);
            p += __shfl_xor_sync(0xffffffffu, p, 8);
            const float ex = expf(p * 0.125f);   // 1/sqrt(64); exact softmax w/o max-sub

            red_v4(g_agg + (size_t)dst * D + col,
                   ex * vj.x, ex * vj.y, ex * vj.z, ex * vj.w);
            if ((lane & 15) == 0)
                red_1(&g_sum[dst * 2 + (lane >> 4)], ex);
        }
    }
}

__global__ void finalize_kernel(float* __restrict__ out) {
    int idx = blockIdx.x * blockDim.x + threadIdx.x;
    if (idx >= NN * 32) return;
    const int n = idx >> 5;
    const int h = (idx & 31) >> 4;
    const float inv = 1.0f / (g_sum[n * 2 + h] + 1e-16f);
    float4 a = ((const float4*)g_agg)[idx];
    float4 o = ((float4*)out)[idx];
    o.x += a.x * inv; o.y += a.y * inv; o.z += a.z * inv; o.w += a.w * inv;
    ((float4*)out)[idx] = o;
}

extern "C" void kernel_launch(void* const* d_in, const int* in_sizes, int n_in,
                              void* d_out, int out_size) {
    const float* x           = (const float*)d_in[0];
    const float* last_update = (const float*)d_in[1];
    const void*  ei          = d_in[2];
    const float* t           = (const float*)d_in[3];
    const float* msg         = (const float*)d_in[4];
    const float* time_w      = (const float*)d_in[5];
    const float* time_b      = (const float*)d_in[6];
    const float* Wq          = (const float*)d_in[7];
    const float* bq          = (const float*)d_in[8];
    const float* Wk          = (const float*)d_in[9];
    const float* bk          = (const float*)d_in[10];
    const float* Wv          = (const float*)d_in[11];
    const float* bv          = (const float*)d_in[12];
    const float* We          = (const float*)d_in[13];
    const float* Ws          = (const float*)d_in[14];
    const float* bs          = (const float*)d_in[15];
    float* out = (float*)d_out;

    const int smem_e1 = TE * SA * 4;     // 83,968 bytes
    const int smem_px = 128 * SX * 4;    // 67,584 bytes
    static int configured = 0;
    if (!configured) {
        cudaFuncSetAttribute(edge_kernel,
                             cudaFuncAttributeMaxDynamicSharedMemorySize, smem_e1);
        cudaFuncSetAttribute(proj_kernel,
                             cudaFuncAttributeMaxDynamicSharedMemorySize, smem_px);
        configured = 1;
    }

    detect_kernel<<<1, 32>>>((const long long*)ei);
    swizzle_we_kernel<<<(EDIM * D + 255) / 256, 256>>>(We);
    swizzle_w_kernel<<<(4 * D * D + 255) / 256, 256>>>(Wq, Wk, Wv, Ws);
    zero_kernel<<<(NN * D + 255) / 256, 256>>>();
    proj_kernel<<<dim3((NN + 127) / 128, 4), 256, smem_px>>>(x, bq, bk, bv, bs, out);
    edge_kernel<<<(NE + TE - 1) / TE, 256, smem_e1>>>(ei, last_update, t, msg,
                                                      time_w, time_b);
    finalize_kernel<<<(NN * 32 + 255) / 256, 256>>>(out);
}

// round 8
// speedup vs baseline: 1.4006x; 1.4006x over previous
#include <cuda_runtime.h>
#include <cuda_fp16.h>

#define NN 50000
#define NE 500000
#define D 128
#define TDIM 32
#define EDIM 160
#define TE 128        // edges per block (edge GEMM)
#define SAH 168       // attr tile smem stride (halves)
#define SXH 136       // x tile smem stride (halves)

// ---- scratch (no cudaMalloc allowed) ----
__device__ __half2 g_qh[NN * 64];
__device__ __half2 g_kh[NN * 64];
__device__ __half2 g_vh[NN * 64];
__device__ float   g_agg[NN * D];
__device__ float   g_sum[NN * 2];
__device__ __half2 g_e[(size_t)NE * 64];     // 128MB fp16 edge projection
__device__ __half2 g_we_h2[80 * D];          // pre-swizzled fp16 We (k-pairs)
__device__ __half2 g_w_h2[4 * 64 * D];       // pre-swizzled fp16 Wq|Wk|Wv|Wskip
__device__ int     g_idx64;

// ---- helpers ----
__device__ __forceinline__ void red_v4(float* p, float a, float b, float c, float d) {
    asm volatile("red.global.add.v4.f32 [%0], {%1,%2,%3,%4};"
                 :: "l"(p), "f"(a), "f"(b), "f"(c), "f"(d) : "memory");
}
__device__ __forceinline__ void red_1(float* p, float a) {
    asm volatile("red.global.add.f32 [%0], %1;" :: "l"(p), "f"(a) : "memory");
}
__device__ __forceinline__ void mma_f16(float* c, const unsigned* a,
                                        unsigned b0, unsigned b1) {
    asm volatile(
        "mma.sync.aligned.m16n8k16.row.col.f32.f16.f16.f32 "
        "{%0,%1,%2,%3}, {%4,%5,%6,%7}, {%8,%9}, {%0,%1,%2,%3};"
        : "+f"(c[0]), "+f"(c[1]), "+f"(c[2]), "+f"(c[3])
        : "r"(a[0]), "r"(a[1]), "r"(a[2]), "r"(a[3]), "r"(b0), "r"(b1));
}

// Detect int64 vs int32 edge_index.
__global__ void detect_kernel(const long long* __restrict__ ei) {
    if (threadIdx.x == 0 && blockIdx.x == 0) {
        bool ok = true;
        #pragma unroll
        for (int i = 0; i < 16; i++) {
            long long v = ei[i];
            if (v < 0 || v >= NN) ok = false;
        }
        g_idx64 = ok ? 1 : 0;
    }
}

// Pre-swizzle We: logical (kpair p, col c) -> storage (p, (c>>6)*64+(c&7)*8+((c>>3)&7)),
// value = half2(We[2p][c], We[2p+1][c]).
__global__ void swizzle_we_kernel(const float* __restrict__ We) {
    int i = blockIdx.x * blockDim.x + threadIdx.x;
    if (i < 80 * D) {
        const int p = i >> 7, c = i & 127;
        const int s = (c >> 6) * 64 + (c & 7) * 8 + ((c >> 3) & 7);
        g_we_h2[p * D + s] = __floats2half2_rn(__ldg(We + (2 * p) * D + c),
                                               __ldg(We + (2 * p + 1) * D + c));
    }
}

// Pre-swizzle the four node-projection weights (64 k-pairs each).
__global__ void swizzle_w_kernel(const float* __restrict__ Wq,
                                 const float* __restrict__ Wk,
                                 const float* __restrict__ Wv,
                                 const float* __restrict__ Ws) {
    int i = blockIdx.x * blockDim.x + threadIdx.x;
    if (i < 4 * 64 * D) {
        const int mat = i >> 13, rem = i & 8191;
        const int p = rem >> 7, c = rem & 127;
        const int s = (c >> 6) * 64 + (c & 7) * 8 + ((c >> 3) & 7);
        const float* W = (mat == 0) ? Wq : (mat == 1) ? Wk : (mat == 2) ? Wv : Ws;
        g_w_h2[mat * 64 * D + p * D + s] =
            __floats2half2_rn(__ldg(W + (2 * p) * D + c), __ldg(W + (2 * p + 1) * D + c));
    }
}

__global__ void zero_kernel() {
    int idx = blockIdx.x * blockDim.x + threadIdx.x;
    if (idx < NN * D) g_agg[idx] = 0.0f;
    if (idx < NN * 2) g_sum[idx] = 0.0f;
}

// ---- proj (fp16 mma): q,k,v,skip = x @ W + b. grid = (nodeTiles, 4 mats) ----
__global__ __launch_bounds__(256, 2) void proj_kernel(
    const float* __restrict__ x,
    const float* __restrict__ bq, const float* __restrict__ bk,
    const float* __restrict__ bv, const float* __restrict__ bs,
    float* __restrict__ out)
{
    extern __shared__ __half sX[];   // [128][SXH] fp16 x tile (34.8KB)
    const int tid = threadIdx.x;
    const int n0  = blockIdx.x * 128;
    const int mat = blockIdx.y;

    for (int i = tid; i < 128 * 32; i += 256) {
        const int n = i >> 5, q = i & 31;
        float4 m = make_float4(0, 0, 0, 0);
        if (n0 + n < NN) m = __ldg((const float4*)(x + (size_t)(n0 + n) * D) + q);
        __half2* p = (__half2*)(sX + n * SXH + 4 * q);
        p[0] = __floats2half2_rn(m.x, m.y);
        p[1] = __floats2half2_rn(m.z, m.w);
    }
    __syncthreads();

    const int wid = tid >> 5, lane = tid & 31;
    const int g = lane >> 2, tg = lane & 3;
    const int wm = wid & 3, wn = wid >> 2;

    float acc[2][8][4];
    #pragma unroll
    for (int mi = 0; mi < 2; mi++)
        #pragma unroll
        for (int ni = 0; ni < 8; ni++)
            #pragma unroll
            for (int r = 0; r < 4; r++) acc[mi][ni][r] = 0.f;

    const __half*  Abase = sX + (wm * 32 + g) * SXH + 2 * tg;
    const __half2* Bb    = g_w_h2 + mat * 64 * D + wn * 64 + g * 8;

    #pragma unroll
    for (int ks = 0; ks < 8; ks++) {             // 8 k16-steps, K=128
        const int k0 = ks * 16;
        unsigned a[2][4];
        #pragma unroll
        for (int mi = 0; mi < 2; mi++) {
            const __half* ap = Abase + mi * 16 * SXH + k0;
            a[mi][0] = *(const unsigned*)(ap);
            a[mi][1] = *(const unsigned*)(ap + 8 * SXH);
            a[mi][2] = *(const unsigned*)(ap + 8);
            a[mi][3] = *(const unsigned*)(ap + 8 * SXH + 8);
        }
        const uint4* bp0 = (const uint4*)(Bb + (size_t)(ks * 8 + tg) * D);
        const uint4* bp1 = (const uint4*)(Bb + (size_t)(ks * 8 + tg + 4) * D);
        const uint4 u0 = __ldg(bp0), u1 = __ldg(bp0 + 1);
        const uint4 v0 = __ldg(bp1), v1 = __ldg(bp1 + 1);
        const unsigned b0[8] = {u0.x, u0.y, u0.z, u0.w, u1.x, u1.y, u1.z, u1.w};
        const unsigned b1[8] = {v0.x, v0.y, v0.z, v0.w, v1.x, v1.y, v1.z, v1.w};
        #pragma unroll
        for (int ni = 0; ni < 8; ni++) {
            mma_f16(acc[0][ni], a[0], b0[ni], b1[ni]);
            mma_f16(acc[1][ni], a[1], b0[ni], b1[ni]);
        }
    }

    const float* bias = (mat == 0) ? bq : (mat == 1) ? bk : (mat == 2) ? bv : bs;

    #pragma unroll
    for (int mi = 0; mi < 2; mi++) {
        const int r0 = n0 + wm * 32 + mi * 16 + g;
        #pragma unroll
        for (int ni = 0; ni < 8; ni++) {
            const int c = wn * 64 + ni * 8 + 2 * tg;
            const float2 bb = __ldg((const float2*)(bias + c));
            if (mat == 3) {
                if (r0 < NN)
                    *(float2*)(out + (size_t)r0 * D + c) =
                        make_float2(acc[mi][ni][0] + bb.x, acc[mi][ni][1] + bb.y);
                if (r0 + 8 < NN)
                    *(float2*)(out + (size_t)(r0 + 8) * D + c) =
                        make_float2(acc[mi][ni][2] + bb.x, acc[mi][ni][3] + bb.y);
            } else {
                __half2* dst = (mat == 0) ? g_qh : (mat == 1) ? g_kh : g_vh;
                const int hc = c >> 1;   // half2 col index
                if (r0 < NN)
                    dst[(size_t)r0 * 64 + hc] =
                        __floats2half2_rn(acc[mi][ni][0] + bb.x, acc[mi][ni][1] + bb.y);
                if (r0 + 8 < NN)
                    dst[(size_t)(r0 + 8) * 64 + hc] =
                        __floats2half2_rn(acc[mi][ni][2] + bb.x, acc[mi][ni][3] + bb.y);
            }
        }
    }
}

// ---- E1: e = attr @ We (fp16 mma, fp16 out) ----
__global__ __launch_bounds__(256, 2) void egemm_kernel(
    const void*  __restrict__ ei_raw,
    const float* __restrict__ last_update,
    const float* __restrict__ t,
    const float* __restrict__ msg,
    const float* __restrict__ time_w,
    const float* __restrict__ time_b)
{
    extern __shared__ __half sA[];      // [TE][SAH] fp16 attr tile (43KB)
    __shared__ float s_rel[TE];

    const int tid = threadIdx.x;
    const int e0  = blockIdx.x * TE;

    if (tid < TE) {
        const int eg = e0 + tid;
        float rel = 0.f;
        if (eg < NE) {
            int src;
            if (g_idx64) src = (int)__ldg((const long long*)ei_raw + eg);
            else         src = __ldg((const int*)ei_raw + eg);
            rel = __ldg(last_update + src) - __ldg(t + eg);
        }
        s_rel[tid] = rel;
    }
    __syncthreads();

    for (int i = tid; i < TE * TDIM; i += 256) {          // time-encode cols [0,32)
        const int e = i >> 5, k = i & 31;
        float v = 0.f;
        if (e0 + e < NE)
            v = cosf(s_rel[e] * __ldg(time_w + k) + __ldg(time_b + k));
        sA[e * SAH + k] = __float2half(v);
    }
    for (int i = tid; i < TE * 32; i += 256) {            // msg cols [32,160)
        const int e = i >> 5, q = i & 31;
        float4 m = make_float4(0, 0, 0, 0);
        if (e0 + e < NE) m = __ldg((const float4*)(msg + (size_t)(e0 + e) * D) + q);
        __half2* p = (__half2*)(sA + e * SAH + TDIM + 4 * q);
        p[0] = __floats2half2_rn(m.x, m.y);
        p[1] = __floats2half2_rn(m.z, m.w);
    }
    __syncthreads();

    const int wid = tid >> 5, lane = tid & 31;
    const int g = lane >> 2, tg = lane & 3;
    const int wm = wid & 3, wn = wid >> 2;

    float acc[2][8][4];
    #pragma unroll
    for (int mi = 0; mi < 2; mi++)
        #pragma unroll
        for (int ni = 0; ni < 8; ni++)
            #pragma unroll
            for (int r = 0; r < 4; r++) acc[mi][ni][r] = 0.f;

    const __half*  Abase = sA + (wm * 32 + g) * SAH + 2 * tg;
    const __half2* Bb    = g_we_h2 + wn * 64 + g * 8;

    #pragma unroll
    for (int ks = 0; ks < 10; ks++) {             // 10 k16-steps, K=160
        const int k0 = ks * 16;
        unsigned a[2][4];
        #pragma unroll
        for (int mi = 0; mi < 2; mi++) {
            const __half* ap = Abase + mi * 16 * SAH + k0;
            a[mi][0] = *(const unsigned*)(ap);
            a[mi][1] = *(const unsigned*)(ap + 8 * SAH);
            a[mi][2] = *(const unsigned*)(ap + 8);
            a[mi][3] = *(const unsigned*)(ap + 8 * SAH + 8);
        }
        const uint4* bp0 = (const uint4*)(Bb + (size_t)(ks * 8 + tg) * D);
        const uint4* bp1 = (const uint4*)(Bb + (size_t)(ks * 8 + tg + 4) * D);
        const uint4 u0 = __ldg(bp0), u1 = __ldg(bp0 + 1);
        const uint4 v0 = __ldg(bp1), v1 = __ldg(bp1 + 1);
        const unsigned b0[8] = {u0.x, u0.y, u0.z, u0.w, u1.x, u1.y, u1.z, u1.w};
        const unsigned b1[8] = {v0.x, v0.y, v0.z, v0.w, v1.x, v1.y, v1.z, v1.w};
        #pragma unroll
        for (int ni = 0; ni < 8; ni++) {
            mma_f16(acc[0][ni], a[0], b0[ni], b1[ni]);
            mma_f16(acc[1][ni], a[1], b0[ni], b1[ni]);
        }
    }

    // write e tile to gmem as half2
    #pragma unroll
    for (int mi = 0; mi < 2; mi++) {
        const int r0 = wm * 32 + mi * 16 + g;
        #pragma unroll
        for (int ni = 0; ni < 8; ni++) {
            const int h = wn * 32 + ni * 4 + tg;
            if (e0 + r0 < NE)
                g_e[(size_t)(e0 + r0) * 64 + h] =
                    __floats2half2_rn(acc[mi][ni][0], acc[mi][ni][1]);
            if (e0 + r0 + 8 < NE)
                g_e[(size_t)(e0 + r0 + 8) * 64 + h] =
                    __floats2half2_rn(acc[mi][ni][2], acc[mi][ni][3]);
        }
    }
}

// ---- E2: attention epilogue (fp16 gathers). Warp = 8 edges; lane = 4 cols. ----
__global__ __launch_bounds__(256) void epilogue_kernel(
    const void* __restrict__ ei_raw)
{
    const int tid  = threadIdx.x;
    const int w    = tid >> 5, lane = tid & 31;
    const int col  = lane * 4;
    const int e0   = blockIdx.x * 64 + w * 8;

    #pragma unroll 4
    for (int ii = 0; ii < 8; ii++) {
        const int eg = e0 + ii;
        if (eg < NE) {
            int src, dst;
            if (g_idx64) {
                const long long* p = (const long long*)ei_raw;
                src = (int)__ldg(p + eg); dst = (int)__ldg(p + NE + eg);
            } else {
                const int* p = (const int*)ei_raw;
                src = __ldg(p + eg); dst = __ldg(p + NE + eg);
            }
            const uint2 eraw = __ldg((const uint2*)(g_e  + (size_t)eg  * 64) + lane);
            const uint2 qraw = __ldg((const uint2*)(g_qh + (size_t)dst * 64) + lane);
            const uint2 kraw = __ldg((const uint2*)(g_kh + (size_t)src * 64) + lane);
            const uint2 vraw = __ldg((const uint2*)(g_vh + (size_t)src * 64) + lane);
            const float2 e01 = __half22float2(*(const __half2*)&eraw.x);
            const float2 e23 = __half22float2(*(const __half2*)&eraw.y);
            const float2 q01 = __half22float2(*(const __half2*)&qraw.x);
            const float2 q23 = __half22float2(*(const __half2*)&qraw.y);
            float2 k01 = __half22float2(*(const __half2*)&kraw.x);
            float2 k23 = __half22float2(*(const __half2*)&kraw.y);
            float2 v01 = __half22float2(*(const __half2*)&vraw.x);
            float2 v23 = __half22float2(*(const __half2*)&vraw.y);
            k01.x += e01.x; k01.y += e01.y; k23.x += e23.x; k23.y += e23.y;
            v01.x += e01.x; v01.y += e01.y; v23.x += e23.x; v23.y += e23.y;

            float p = q01.x * k01.x + q01.y * k01.y + q23.x * k23.x + q23.y * k23.y;
            p += __shfl_xor_sync(0xffffffffu, p, 1);
            p += __shfl_xor_sync(0xffffffffu, p, 2);
            p += __shfl_xor_sync(0xffffffffu, p, 4);
            p += __shfl_xor_sync(0xffffffffu, p, 8);
            const float ex = expf(p * 0.125f);   // 1/sqrt(64); exact softmax w/o max-sub

            red_v4(g_agg + (size_t)dst * D + col,
                   ex * v01.x, ex * v01.y, ex * v23.x, ex * v23.y);
            if ((lane & 15) == 0)
                red_1(&g_sum[dst * 2 + (lane >> 4)], ex);
        }
    }
}

__global__ void finalize_kernel(float* __restrict__ out) {
    int idx = blockIdx.x * blockDim.x + threadIdx.x;
    if (idx >= NN * 32) return;
    const int n = idx >> 5;
    const int h = (idx & 31) >> 4;
    const float inv = 1.0f / (g_sum[n * 2 + h] + 1e-16f);
    float4 a = ((const float4*)g_agg)[idx];
    float4 o = ((float4*)out)[idx];
    o.x += a.x * inv; o.y += a.y * inv; o.z += a.z * inv; o.w += a.w * inv;
    ((float4*)out)[idx] = o;
}

extern "C" void kernel_launch(void* const* d_in, const int* in_sizes, int n_in,
                              void* d_out, int out_size) {
    const float* x           = (const float*)d_in[0];
    const float* last_update = (const float*)d_in[1];
    const void*  ei          = d_in[2];
    const float* t           = (const float*)d_in[3];
    const float* msg         = (const float*)d_in[4];
    const float* time_w      = (const float*)d_in[5];
    const float* time_b      = (const float*)d_in[6];
    const float* Wq          = (const float*)d_in[7];
    const float* bq          = (const float*)d_in[8];
    const float* Wk          = (const float*)d_in[9];
    const float* bk          = (const float*)d_in[10];
    const float* Wv          = (const float*)d_in[11];
    const float* bv          = (const float*)d_in[12];
    const float* We          = (const float*)d_in[13];
    const float* Ws          = (const float*)d_in[14];
    const float* bs          = (const float*)d_in[15];
    float* out = (float*)d_out;

    const int smem_e1 = TE * SAH * 2;     // 43,008 bytes
    const int smem_px = 128 * SXH * 2;    // 34,816 bytes
    static int configured = 0;
    if (!configured) {
        cudaFuncSetAttribute(egemm_kernel,
                             cudaFuncAttributeMaxDynamicSharedMemorySize, smem_e1);
        cudaFuncSetAttribute(proj_kernel,
                             cudaFuncAttributeMaxDynamicSharedMemorySize, smem_px);
        configured = 1;
    }

    detect_kernel<<<1, 32>>>((const long long*)ei);
    swizzle_we_kernel<<<(80 * D + 255) / 256, 256>>>(We);
    swizzle_w_kernel<<<(4 * 64 * D + 255) / 256, 256>>>(Wq, Wk, Wv, Ws);
    zero_kernel<<<(NN * D + 255) / 256, 256>>>();
    proj_kernel<<<dim3((NN + 127) / 128, 4), 256, smem_px>>>(x, bq, bk, bv, bs, out);
    egemm_kernel<<<(NE + TE - 1) / TE, 256, smem_e1>>>(ei, last_update, t, msg,
                                                       time_w, time_b);
    epilogue_kernel<<<(NE + 63) / 64, 256>>>(ei);
    finalize_kernel<<<(NN * 32 + 255) / 256, 256>>>(out);
}

// round 9
// speedup vs baseline: 1.4371x; 1.0260x over previous
#include <cuda_runtime.h>
#include <cuda_fp16.h>

#define NN 50000
#define NE 500000
#define D 128
#define TDIM 32
#define EDIM 160
#define TE 128        // edges per block (edge GEMM)
#define SAH 168       // attr tile smem stride (halves)
#define SXH 136       // x tile smem stride (halves)

// ---- scratch (no cudaMalloc allowed) ----
__device__ __half2 g_qh[NN * 64];
__device__ __half2 g_kh[NN * 64];
__device__ __half2 g_vh[NN * 64];
__device__ float   g_agg[NN * D];
__device__ float   g_sum[NN * 2];
__device__ __half2 g_e[(size_t)NE * 64];     // 128MB fp16 edge projection
__device__ __half2 g_we_h2[80 * D];          // pre-swizzled fp16 We (k-pairs)
__device__ __half2 g_w_h2[4 * 64 * D];       // pre-swizzled fp16 Wq|Wk|Wv|Wskip
__device__ int     g_idx64;

// ---- helpers ----
__device__ __forceinline__ void red_v4(float* p, float a, float b, float c, float d) {
    asm volatile("red.global.add.v4.f32 [%0], {%1,%2,%3,%4};"
                 :: "l"(p), "f"(a), "f"(b), "f"(c), "f"(d) : "memory");
}
__device__ __forceinline__ void red_1(float* p, float a) {
    asm volatile("red.global.add.f32 [%0], %1;" :: "l"(p), "f"(a) : "memory");
}
__device__ __forceinline__ void mma_f16(float* c, const unsigned* a,
                                        unsigned b0, unsigned b1) {
    asm volatile(
        "mma.sync.aligned.m16n8k16.row.col.f32.f16.f16.f32 "
        "{%0,%1,%2,%3}, {%4,%5,%6,%7}, {%8,%9}, {%0,%1,%2,%3};"
        : "+f"(c[0]), "+f"(c[1]), "+f"(c[2]), "+f"(c[3])
        : "r"(a[0]), "r"(a[1]), "r"(a[2]), "r"(a[3]), "r"(b0), "r"(b1));
}

// ---- prep: detect idx width + pre-swizzle all weights (one launch) ----
__global__ void prep_kernel(const long long* __restrict__ ei,
                            const float* __restrict__ We,
                            const float* __restrict__ Wq,
                            const float* __restrict__ Wk,
                            const float* __restrict__ Wv,
                            const float* __restrict__ Ws) {
    const int i = blockIdx.x * blockDim.x + threadIdx.x;
    if (i == 0) {
        bool ok = true;
        #pragma unroll
        for (int j = 0; j < 16; j++) {
            long long v = ei[j];
            if (v < 0 || v >= NN) ok = false;
        }
        g_idx64 = ok ? 1 : 0;
    }
    if (i < 80 * D) {                     // We: 80 k-pairs x 128 cols
        const int p = i >> 7, c = i & 127;
        const int s = (c >> 6) * 64 + (c & 7) * 8 + ((c >> 3) & 7);
        g_we_h2[p * D + s] = __floats2half2_rn(__ldg(We + (2 * p) * D + c),
                                               __ldg(We + (2 * p + 1) * D + c));
    }
    if (i < 4 * 64 * D) {                 // Wq|Wk|Wv|Ws: 64 k-pairs each
        const int mat = i >> 13, rem = i & 8191;
        const int p = rem >> 7, c = rem & 127;
        const int s = (c >> 6) * 64 + (c & 7) * 8 + ((c >> 3) & 7);
        const float* W = (mat == 0) ? Wq : (mat == 1) ? Wk : (mat == 2) ? Wv : Ws;
        g_w_h2[mat * 64 * D + p * D + s] =
            __floats2half2_rn(__ldg(W + (2 * p) * D + c), __ldg(W + (2 * p + 1) * D + c));
    }
}

// ---- zero: vectorized grid-stride ----
__global__ void zero_kernel() {
    const float4 z = make_float4(0, 0, 0, 0);
    const int stride = gridDim.x * blockDim.x;
    for (int i = blockIdx.x * blockDim.x + threadIdx.x; i < NN * 32; i += stride)
        ((float4*)g_agg)[i] = z;
    for (int i = blockIdx.x * blockDim.x + threadIdx.x; i < NN / 2; i += stride)
        ((float4*)g_sum)[i] = z;
}

// ---- proj (fp16 mma): q,k,v,skip = x @ W + b. grid = (nodeTiles, 4 mats) ----
__global__ __launch_bounds__(256, 2) void proj_kernel(
    const float* __restrict__ x,
    const float* __restrict__ bq, const float* __restrict__ bk,
    const float* __restrict__ bv, const float* __restrict__ bs,
    float* __restrict__ out)
{
    extern __shared__ __half sX[];   // [128][SXH] fp16 x tile (34.8KB)
    const int tid = threadIdx.x;
    const int n0  = blockIdx.x * 128;
    const int mat = blockIdx.y;

    for (int i = tid; i < 128 * 32; i += 256) {
        const int n = i >> 5, q = i & 31;
        float4 m = make_float4(0, 0, 0, 0);
        if (n0 + n < NN) m = __ldg((const float4*)(x + (size_t)(n0 + n) * D) + q);
        __half2* p = (__half2*)(sX + n * SXH + 4 * q);
        p[0] = __floats2half2_rn(m.x, m.y);
        p[1] = __floats2half2_rn(m.z, m.w);
    }
    __syncthreads();

    const int wid = tid >> 5, lane = tid & 31;
    const int g = lane >> 2, tg = lane & 3;
    const int wm = wid & 3, wn = wid >> 2;

    float acc[2][8][4];
    #pragma unroll
    for (int mi = 0; mi < 2; mi++)
        #pragma unroll
        for (int ni = 0; ni < 8; ni++)
            #pragma unroll
            for (int r = 0; r < 4; r++) acc[mi][ni][r] = 0.f;

    const __half*  Abase = sX + (wm * 32 + g) * SXH + 2 * tg;
    const __half2* Bb    = g_w_h2 + mat * 64 * D + wn * 64 + g * 8;

    #pragma unroll
    for (int ks = 0; ks < 8; ks++) {             // 8 k16-steps, K=128
        const int k0 = ks * 16;
        unsigned a[2][4];
        #pragma unroll
        for (int mi = 0; mi < 2; mi++) {
            const __half* ap = Abase + mi * 16 * SXH + k0;
            a[mi][0] = *(const unsigned*)(ap);
            a[mi][1] = *(const unsigned*)(ap + 8 * SXH);
            a[mi][2] = *(const unsigned*)(ap + 8);
            a[mi][3] = *(const unsigned*)(ap + 8 * SXH + 8);
        }
        const uint4* bp0 = (const uint4*)(Bb + (size_t)(ks * 8 + tg) * D);
        const uint4* bp1 = (const uint4*)(Bb + (size_t)(ks * 8 + tg + 4) * D);
        const uint4 u0 = __ldg(bp0), u1 = __ldg(bp0 + 1);
        const uint4 v0 = __ldg(bp1), v1 = __ldg(bp1 + 1);
        const unsigned b0[8] = {u0.x, u0.y, u0.z, u0.w, u1.x, u1.y, u1.z, u1.w};
        const unsigned b1[8] = {v0.x, v0.y, v0.z, v0.w, v1.x, v1.y, v1.z, v1.w};
        #pragma unroll
        for (int ni = 0; ni < 8; ni++) {
            mma_f16(acc[0][ni], a[0], b0[ni], b1[ni]);
            mma_f16(acc[1][ni], a[1], b0[ni], b1[ni]);
        }
    }

    const float* bias = (mat == 0) ? bq : (mat == 1) ? bk : (mat == 2) ? bv : bs;

    #pragma unroll
    for (int mi = 0; mi < 2; mi++) {
        const int r0 = n0 + wm * 32 + mi * 16 + g;
        #pragma unroll
        for (int ni = 0; ni < 8; ni++) {
            const int c = wn * 64 + ni * 8 + 2 * tg;
            const float2 bb = __ldg((const float2*)(bias + c));
            if (mat == 3) {
                if (r0 < NN)
                    *(float2*)(out + (size_t)r0 * D + c) =
                        make_float2(acc[mi][ni][0] + bb.x, acc[mi][ni][1] + bb.y);
                if (r0 + 8 < NN)
                    *(float2*)(out + (size_t)(r0 + 8) * D + c) =
                        make_float2(acc[mi][ni][2] + bb.x, acc[mi][ni][3] + bb.y);
            } else {
                __half2* dst = (mat == 0) ? g_qh : (mat == 1) ? g_kh : g_vh;
                const int hc = c >> 1;
                if (r0 < NN)
                    dst[(size_t)r0 * 64 + hc] =
                        __floats2half2_rn(acc[mi][ni][0] + bb.x, acc[mi][ni][1] + bb.y);
                if (r0 + 8 < NN)
                    dst[(size_t)(r0 + 8) * 64 + hc] =
                        __floats2half2_rn(acc[mi][ni][2] + bb.x, acc[mi][ni][3] + bb.y);
            }
        }
    }
}

// ---- E1: e = attr @ We (fp16 mma, fp16 out) ----
__global__ __launch_bounds__(256, 2) void egemm_kernel(
    const void*  __restrict__ ei_raw,
    const float* __restrict__ last_update,
    const float* __restrict__ t,
    const float* __restrict__ msg,
    const float* __restrict__ time_w,
    const float* __restrict__ time_b)
{
    extern __shared__ __half sA[];      // [TE][SAH] fp16 attr tile (43KB)
    __shared__ float s_rel[TE];

    const int tid = threadIdx.x;
    const int e0  = blockIdx.x * TE;

    if (tid < TE) {
        const int eg = e0 + tid;
        float rel = 0.f;
        if (eg < NE) {
            int src;
            if (g_idx64) src = (int)__ldg((const long long*)ei_raw + eg);
            else         src = __ldg((const int*)ei_raw + eg);
            rel = __ldg(last_update + src) - __ldg(t + eg);
        }
        s_rel[tid] = rel;
    }
    __syncthreads();

    for (int i = tid; i < TE * TDIM; i += 256) {          // time-encode cols [0,32)
        const int e = i >> 5, k = i & 31;
        float v = 0.f;
        if (e0 + e < NE)
            v = cosf(s_rel[e] * __ldg(time_w + k) + __ldg(time_b + k));
        sA[e * SAH + k] = __float2half(v);
    }
    for (int i = tid; i < TE * 32; i += 256) {            // msg cols [32,160)
        const int e = i >> 5, q = i & 31;
        float4 m = make_float4(0, 0, 0, 0);
        if (e0 + e < NE) m = __ldg((const float4*)(msg + (size_t)(e0 + e) * D) + q);
        __half2* p = (__half2*)(sA + e * SAH + TDIM + 4 * q);
        p[0] = __floats2half2_rn(m.x, m.y);
        p[1] = __floats2half2_rn(m.z, m.w);
    }
    __syncthreads();

    const int wid = tid >> 5, lane = tid & 31;
    const int g = lane >> 2, tg = lane & 3;
    const int wm = wid & 3, wn = wid >> 2;

    float acc[2][8][4];
    #pragma unroll
    for (int mi = 0; mi < 2; mi++)
        #pragma unroll
        for (int ni = 0; ni < 8; ni++)
            #pragma unroll
            for (int r = 0; r < 4; r++) acc[mi][ni][r] = 0.f;

    const __half*  Abase = sA + (wm * 32 + g) * SAH + 2 * tg;
    const __half2* Bb    = g_we_h2 + wn * 64 + g * 8;

    #pragma unroll
    for (int ks = 0; ks < 10; ks++) {             // 10 k16-steps, K=160
        const int k0 = ks * 16;
        unsigned a[2][4];
        #pragma unroll
        for (int mi = 0; mi < 2; mi++) {
            const __half* ap = Abase + mi * 16 * SAH + k0;
            a[mi][0] = *(const unsigned*)(ap);
            a[mi][1] = *(const unsigned*)(ap + 8 * SAH);
            a[mi][2] = *(const unsigned*)(ap + 8);
            a[mi][3] = *(const unsigned*)(ap + 8 * SAH + 8);
        }
        const uint4* bp0 = (const uint4*)(Bb + (size_t)(ks * 8 + tg) * D);
        const uint4* bp1 = (const uint4*)(Bb + (size_t)(ks * 8 + tg + 4) * D);
        const uint4 u0 = __ldg(bp0), u1 = __ldg(bp0 + 1);
        const uint4 v0 = __ldg(bp1), v1 = __ldg(bp1 + 1);
        const unsigned b0[8] = {u0.x, u0.y, u0.z, u0.w, u1.x, u1.y, u1.z, u1.w};
        const unsigned b1[8] = {v0.x, v0.y, v0.z, v0.w, v1.x, v1.y, v1.z, v1.w};
        #pragma unroll
        for (int ni = 0; ni < 8; ni++) {
            mma_f16(acc[0][ni], a[0], b0[ni], b1[ni]);
            mma_f16(acc[1][ni], a[1], b0[ni], b1[ni]);
        }
    }

    // write e tile to gmem as half2
    #pragma unroll
    for (int mi = 0; mi < 2; mi++) {
        const int r0 = wm * 32 + mi * 16 + g;
        #pragma unroll
        for (int ni = 0; ni < 8; ni++) {
            const int h = wn * 32 + ni * 4 + tg;
            if (e0 + r0 < NE)
                g_e[(size_t)(e0 + r0) * 64 + h] =
                    __floats2half2_rn(acc[mi][ni][0], acc[mi][ni][1]);
            if (e0 + r0 + 8 < NE)
                g_e[(size_t)(e0 + r0 + 8) * 64 + h] =
                    __floats2half2_rn(acc[mi][ni][2], acc[mi][ni][3]);
        }
    }
}

// ---- E2: attention epilogue. Warp = 8 edges (indices pre-loaded); lane = 4 cols. ----
__global__ __launch_bounds__(256) void epilogue_kernel(
    const void* __restrict__ ei_raw)
{
    const int tid  = threadIdx.x;
    const int w    = tid >> 5, lane = tid & 31;
    const int col  = lane * 4;
    const int e0   = blockIdx.x * 64 + w * 8;
    const bool full = (e0 + 8 <= NE);
    const int idx64 = g_idx64;

    // phase A: all 16 index loads in flight up-front
    int srcs[8], dsts[8];
    if (idx64) {
        const long long* p = (const long long*)ei_raw;
        #pragma unroll
        for (int ii = 0; ii < 8; ii++) {
            const int eg = e0 + ii;
            const bool v = full || (eg < NE);
            srcs[ii] = v ? (int)__ldg(p + eg) : 0;
            dsts[ii] = v ? (int)__ldg(p + NE + eg) : 0;
        }
    } else {
        const int* p = (const int*)ei_raw;
        #pragma unroll
        for (int ii = 0; ii < 8; ii++) {
            const int eg = e0 + ii;
            const bool v = full || (eg < NE);
            srcs[ii] = v ? __ldg(p + eg) : 0;
            dsts[ii] = v ? __ldg(p + NE + eg) : 0;
        }
    }

    // phase B: fully unrolled body — loads from different edges overlap
    #pragma unroll
    for (int ii = 0; ii < 8; ii++) {
        const int eg = e0 + ii;
        if (full || eg < NE) {
            const int src = srcs[ii], dst = dsts[ii];
            const uint2 eraw = __ldg((const uint2*)(g_e  + (size_t)eg  * 64) + lane);
            const uint2 qraw = __ldg((const uint2*)(g_qh + (size_t)dst * 64) + lane);
            const uint2 kraw = __ldg((const uint2*)(g_kh + (size_t)src * 64) + lane);
            const uint2 vraw = __ldg((const uint2*)(g_vh + (size_t)src * 64) + lane);
            const float2 e01 = __half22float2(*(const __half2*)&eraw.x);
            const float2 e23 = __half22float2(*(const __half2*)&eraw.y);
            const float2 q01 = __half22float2(*(const __half2*)&qraw.x);
            const float2 q23 = __half22float2(*(const __half2*)&qraw.y);
            float2 k01 = __half22float2(*(const __half2*)&kraw.x);
            float2 k23 = __half22float2(*(const __half2*)&kraw.y);
            float2 v01 = __half22float2(*(const __half2*)&vraw.x);
            float2 v23 = __half22float2(*(const __half2*)&vraw.y);
            k01.x += e01.x; k01.y += e01.y; k23.x += e23.x; k23.y += e23.y;
            v01.x += e01.x; v01.y += e01.y; v23.x += e23.x; v23.y += e23.y;

            float p = q01.x * k01.x + q01.y * k01.y + q23.x * k23.x + q23.y * k23.y;
            p += __shfl_xor_sync(0xffffffffu, p, 1);
            p += __shfl_xor_sync(0xffffffffu, p, 2);
            p += __shfl_xor_sync(0xffffffffu, p, 4);
            p += __shfl_xor_sync(0xffffffffu, p, 8);
            const float ex = expf(p * 0.125f);   // 1/sqrt(64); exact softmax w/o max-sub

            red_v4(g_agg + (size_t)dst * D + col,
                   ex * v01.x, ex * v01.y, ex * v23.x, ex * v23.y);
            if ((lane & 15) == 0)
                red_1(&g_sum[dst * 2 + (lane >> 4)], ex);
        }
    }
}

__global__ void finalize_kernel(float* __restrict__ out) {
    int idx = blockIdx.x * blockDim.x + threadIdx.x;
    if (idx >= NN * 32) return;
    const int n = idx >> 5;
    const int h = (idx & 31) >> 4;
    const float inv = 1.0f / (g_sum[n * 2 + h] + 1e-16f);
    float4 a = ((const float4*)g_agg)[idx];
    float4 o = ((float4*)out)[idx];
    o.x += a.x * inv; o.y += a.y * inv; o.z += a.z * inv; o.w += a.w * inv;
    ((float4*)out)[idx] = o;
}

extern "C" void kernel_launch(void* const* d_in, const int* in_sizes, int n_in,
                              void* d_out, int out_size) {
    const float* x           = (const float*)d_in[0];
    const float* last_update = (const float*)d_in[1];
    const void*  ei          = d_in[2];
    const float* t           = (const float*)d_in[3];
    const float* msg         = (const float*)d_in[4];
    const float* time_w      = (const float*)d_in[5];
    const float* time_b      = (const float*)d_in[6];
    const float* Wq          = (const float*)d_in[7];
    const float* bq          = (const float*)d_in[8];
    const float* Wk          = (const float*)d_in[9];
    const float* bk          = (const float*)d_in[10];
    const float* Wv          = (const float*)d_in[11];
    const float* bv          = (const float*)d_in[12];
    const float* We          = (const float*)d_in[13];
    const float* Ws          = (const float*)d_in[14];
    const float* bs          = (const float*)d_in[15];
    float* out = (float*)d_out;

    const int smem_e1 = TE * SAH * 2;     // 43,008 bytes
    const int smem_px = 128 * SXH * 2;    // 34,816 bytes
    static int configured = 0;
    if (!configured) {
        cudaFuncSetAttribute(egemm_kernel,
                             cudaFuncAttributeMaxDynamicSharedMemorySize, smem_e1);
        cudaFuncSetAttribute(proj_kernel,
                             cudaFuncAttributeMaxDynamicSharedMemorySize, smem_px);
        configured = 1;
    }

    prep_kernel<<<(4 * 64 * D + 255) / 256, 256>>>((const long long*)ei, We,
                                                   Wq, Wk, Wv, Ws);
    zero_kernel<<<592, 256>>>();
    proj_kernel<<<dim3((NN + 127) / 128, 4), 256, smem_px>>>(x, bq, bk, bv, bs, out);
    egemm_kernel<<<(NE + TE - 1) / TE, 256, smem_e1>>>(ei, last_update, t, msg,
                                                       time_w, time_b);
    epilogue_kernel<<<(NE + 63) / 64, 256>>>(ei);
    finalize_kernel<<<(NN * 32 + 255) / 256, 256>>>(out);
}

// round 10
// speedup vs baseline: 1.6318x; 1.1355x over previous
#include <cuda_runtime.h>
#include <cuda_fp16.h>

#define NN 50000
#define NE 500000
#define D 128
#define TDIM 32
#define EDIM 160
#define TE 64         // edges per block (edge GEMM)
#define SAH 168       // attr tile smem stride (halves)
#define SXH 136       // x tile smem stride (halves)

// ---- scratch (no cudaMalloc allowed) ----
__device__ __half2 g_qh[NN * 64];
__device__ __half2 g_kh[NN * 64];
__device__ __half2 g_vh[NN * 64];
__device__ float   g_agg[NN * D];
__device__ float   g_sum[NN * 2];
__device__ __half2 g_e[(size_t)NE * 64];     // 128MB fp16 edge projection
__device__ __half2 g_we_h2[80 * D];          // pre-swizzled fp16 We (k-pairs)
__device__ __half2 g_w_h2[4 * 64 * D];       // pre-swizzled fp16 Wq|Wk|Wv|Wskip
__device__ int     g_idx64;

// ---- helpers ----
__device__ __forceinline__ void red_v4(float* p, float a, float b, float c, float d) {
    asm volatile("red.global.add.v4.f32 [%0], {%1,%2,%3,%4};"
                 :: "l"(p), "f"(a), "f"(b), "f"(c), "f"(d) : "memory");
}
__device__ __forceinline__ void red_1(float* p, float a) {
    asm volatile("red.global.add.f32 [%0], %1;" :: "l"(p), "f"(a) : "memory");
}
__device__ __forceinline__ void mma_f16(float* c, const unsigned* a,
                                        unsigned b0, unsigned b1) {
    asm volatile(
        "mma.sync.aligned.m16n8k16.row.col.f32.f16.f16.f32 "
        "{%0,%1,%2,%3}, {%4,%5,%6,%7}, {%8,%9}, {%0,%1,%2,%3};"
        : "+f"(c[0]), "+f"(c[1]), "+f"(c[2]), "+f"(c[3])
        : "r"(a[0]), "r"(a[1]), "r"(a[2]), "r"(a[3]), "r"(b0), "r"(b1));
}

// ---- prep: detect idx width + pre-swizzle all weights (one launch) ----
__global__ void prep_kernel(const long long* __restrict__ ei,
                            const float* __restrict__ We,
                            const float* __restrict__ Wq,
                            const float* __restrict__ Wk,
                            const float* __restrict__ Wv,
                            const float* __restrict__ Ws) {
    const int i = blockIdx.x * blockDim.x + threadIdx.x;
    if (i == 0) {
        bool ok = true;
        #pragma unroll
        for (int j = 0; j < 16; j++) {
            long long v = ei[j];
            if (v < 0 || v >= NN) ok = false;
        }
        g_idx64 = ok ? 1 : 0;
    }
    if (i < 80 * D) {                     // We: 80 k-pairs x 128 cols
        const int p = i >> 7, c = i & 127;
        const int s = (c >> 6) * 64 + (c & 7) * 8 + ((c >> 3) & 7);
        g_we_h2[p * D + s] = __floats2half2_rn(__ldg(We + (2 * p) * D + c),
                                               __ldg(We + (2 * p + 1) * D + c));
    }
    if (i < 4 * 64 * D) {                 // Wq|Wk|Wv|Ws: 64 k-pairs each
        const int mat = i >> 13, rem = i & 8191;
        const int p = rem >> 7, c = rem & 127;
        const int s = (c >> 6) * 64 + (c & 7) * 8 + ((c >> 3) & 7);
        const float* W = (mat == 0) ? Wq : (mat == 1) ? Wk : (mat == 2) ? Wv : Ws;
        g_w_h2[mat * 64 * D + p * D + s] =
            __floats2half2_rn(__ldg(W + (2 * p) * D + c), __ldg(W + (2 * p + 1) * D + c));
    }
}

// ---- zero: vectorized grid-stride ----
__global__ void zero_kernel() {
    const float4 z = make_float4(0, 0, 0, 0);
    const int stride = gridDim.x * blockDim.x;
    for (int i = blockIdx.x * blockDim.x + threadIdx.x; i < NN * 32; i += stride)
        ((float4*)g_agg)[i] = z;
    for (int i = blockIdx.x * blockDim.x + threadIdx.x; i < NN / 2; i += stride)
        ((float4*)g_sum)[i] = z;
}

// ---- proj (fp16 mma): q,k,v,skip = x @ W + b. grid = (nodeTiles, 4 mats) ----
__global__ __launch_bounds__(256, 2) void proj_kernel(
    const float* __restrict__ x,
    const float* __restrict__ bq, const float* __restrict__ bk,
    const float* __restrict__ bv, const float* __restrict__ bs,
    float* __restrict__ out)
{
    extern __shared__ __half sX[];   // [128][SXH] fp16 x tile (34.8KB)
    const int tid = threadIdx.x;
    const int n0  = blockIdx.x * 128;
    const int mat = blockIdx.y;

    for (int i = tid; i < 128 * 32; i += 256) {
        const int n = i >> 5, q = i & 31;
        float4 m = make_float4(0, 0, 0, 0);
        if (n0 + n < NN) m = __ldg((const float4*)(x + (size_t)(n0 + n) * D) + q);
        __half2* p = (__half2*)(sX + n * SXH + 4 * q);
        p[0] = __floats2half2_rn(m.x, m.y);
        p[1] = __floats2half2_rn(m.z, m.w);
    }
    __syncthreads();

    const int wid = tid >> 5, lane = tid & 31;
    const int g = lane >> 2, tg = lane & 3;
    const int wm = wid & 3, wn = wid >> 2;

    float acc[2][8][4];
    #pragma unroll
    for (int mi = 0; mi < 2; mi++)
        #pragma unroll
        for (int ni = 0; ni < 8; ni++)
            #pragma unroll
            for (int r = 0; r < 4; r++) acc[mi][ni][r] = 0.f;

    const __half*  Abase = sX + (wm * 32 + g) * SXH + 2 * tg;
    const __half2* Bb    = g_w_h2 + mat * 64 * D + wn * 64 + g * 8;

    #pragma unroll
    for (int ks = 0; ks < 8; ks++) {             // 8 k16-steps, K=128
        const int k0 = ks * 16;
        unsigned a[2][4];
        #pragma unroll
        for (int mi = 0; mi < 2; mi++) {
            const __half* ap = Abase + mi * 16 * SXH + k0;
            a[mi][0] = *(const unsigned*)(ap);
            a[mi][1] = *(const unsigned*)(ap + 8 * SXH);
            a[mi][2] = *(const unsigned*)(ap + 8);
            a[mi][3] = *(const unsigned*)(ap + 8 * SXH + 8);
        }
        const uint4* bp0 = (const uint4*)(Bb + (size_t)(ks * 8 + tg) * D);
        const uint4* bp1 = (const uint4*)(Bb + (size_t)(ks * 8 + tg + 4) * D);
        const uint4 u0 = __ldg(bp0), u1 = __ldg(bp0 + 1);
        const uint4 v0 = __ldg(bp1), v1 = __ldg(bp1 + 1);
        const unsigned b0[8] = {u0.x, u0.y, u0.z, u0.w, u1.x, u1.y, u1.z, u1.w};
        const unsigned b1[8] = {v0.x, v0.y, v0.z, v0.w, v1.x, v1.y, v1.z, v1.w};
        #pragma unroll
        for (int ni = 0; ni < 8; ni++) {
            mma_f16(acc[0][ni], a[0], b0[ni], b1[ni]);
            mma_f16(acc[1][ni], a[1], b0[ni], b1[ni]);
        }
    }

    const float* bias = (mat == 0) ? bq : (mat == 1) ? bk : (mat == 2) ? bv : bs;

    #pragma unroll
    for (int mi = 0; mi < 2; mi++) {
        const int r0 = n0 + wm * 32 + mi * 16 + g;
        #pragma unroll
        for (int ni = 0; ni < 8; ni++) {
            const int c = wn * 64 + ni * 8 + 2 * tg;
            const float2 bb = __ldg((const float2*)(bias + c));
            if (mat == 3) {
                if (r0 < NN)
                    *(float2*)(out + (size_t)r0 * D + c) =
                        make_float2(acc[mi][ni][0] + bb.x, acc[mi][ni][1] + bb.y);
                if (r0 + 8 < NN)
                    *(float2*)(out + (size_t)(r0 + 8) * D + c) =
                        make_float2(acc[mi][ni][2] + bb.x, acc[mi][ni][3] + bb.y);
            } else {
                __half2* dst = (mat == 0) ? g_qh : (mat == 1) ? g_kh : g_vh;
                const int hc = c >> 1;
                if (r0 < NN)
                    dst[(size_t)r0 * 64 + hc] =
                        __floats2half2_rn(acc[mi][ni][0] + bb.x, acc[mi][ni][1] + bb.y);
                if (r0 + 8 < NN)
                    dst[(size_t)(r0 + 8) * 64 + hc] =
                        __floats2half2_rn(acc[mi][ni][2] + bb.x, acc[mi][ni][3] + bb.y);
            }
        }
    }
}

// ---- E1: e = attr @ We. TE=64, warp tile 32x32, 4 CTAs/SM ----
__global__ __launch_bounds__(256, 4) void egemm_kernel(
    const void*  __restrict__ ei_raw,
    const float* __restrict__ last_update,
    const float* __restrict__ t,
    const float* __restrict__ msg,
    const float* __restrict__ time_w,
    const float* __restrict__ time_b)
{
    extern __shared__ __half sA[];      // [TE][SAH] fp16 attr tile (21.5KB)
    __shared__ float s_rel[TE];

    const int tid = threadIdx.x;
    const int e0  = blockIdx.x * TE;

    if (tid < TE) {
        const int eg = e0 + tid;
        float rel = 0.f;
        if (eg < NE) {
            int src;
            if (g_idx64) src = (int)__ldg((const long long*)ei_raw + eg);
            else         src = __ldg((const int*)ei_raw + eg);
            rel = __ldg(last_update + src) - __ldg(t + eg);
        }
        s_rel[tid] = rel;
    }
    __syncthreads();

    for (int i = tid; i < TE * TDIM; i += 256) {          // time-encode cols [0,32)
        const int e = i >> 5, k = i & 31;
        float v = 0.f;
        if (e0 + e < NE)
            v = cosf(s_rel[e] * __ldg(time_w + k) + __ldg(time_b + k));
        sA[e * SAH + k] = __float2half(v);
    }
    for (int i = tid; i < TE * 32; i += 256) {            // msg cols [32,160)
        const int e = i >> 5, q = i & 31;
        float4 m = make_float4(0, 0, 0, 0);
        if (e0 + e < NE) m = __ldg((const float4*)(msg + (size_t)(e0 + e) * D) + q);
        __half2* p = (__half2*)(sA + e * SAH + TDIM + 4 * q);
        p[0] = __floats2half2_rn(m.x, m.y);
        p[1] = __floats2half2_rn(m.z, m.w);
    }
    __syncthreads();

    // GEMM: 8 warps = 2(M) x 4(N); warp tile 32x32.
    const int wid = tid >> 5, lane = tid & 31;
    const int g = lane >> 2, tg = lane & 3;
    const int wm = wid & 1, wn = wid >> 1;       // wn 0..3
    const int half = wn >> 1, w1 = wn & 1;       // 64-col half, quarter within

    float acc[2][4][4];
    #pragma unroll
    for (int mi = 0; mi < 2; mi++)
        #pragma unroll
        for (int ni = 0; ni < 4; ni++)
            #pragma unroll
            for (int r = 0; r < 4; r++) acc[mi][ni][r] = 0.f;

    const __half*  Abase = sA + (wm * 32 + g) * SAH + 2 * tg;
    // swizzled storage: warp's 4 n-slots are contiguous half2s -> one LDG.128/row
    const __half2* Bb    = g_we_h2 + half * 64 + g * 8 + w1 * 4;

    #pragma unroll
    for (int ks = 0; ks < 10; ks++) {             // 10 k16-steps, K=160
        const int k0 = ks * 16;
        unsigned a[2][4];
        #pragma unroll
        for (int mi = 0; mi < 2; mi++) {
            const __half* ap = Abase + mi * 16 * SAH + k0;
            a[mi][0] = *(const unsigned*)(ap);
            a[mi][1] = *(const unsigned*)(ap + 8 * SAH);
            a[mi][2] = *(const unsigned*)(ap + 8);
            a[mi][3] = *(const unsigned*)(ap + 8 * SAH + 8);
        }
        const uint4 u = __ldg((const uint4*)(Bb + (size_t)(ks * 8 + tg) * D));
        const uint4 v = __ldg((const uint4*)(Bb + (size_t)(ks * 8 + tg + 4) * D));
        const unsigned b0[4] = {u.x, u.y, u.z, u.w};
        const unsigned b1[4] = {v.x, v.y, v.z, v.w};
        #pragma unroll
        for (int ni = 0; ni < 4; ni++) {
            mma_f16(acc[0][ni], a[0], b0[ni], b1[ni]);
            mma_f16(acc[1][ni], a[1], b0[ni], b1[ni]);
        }
    }

    // write e tile to gmem as half2 (logical col = half*64 + (w1*4+ni)*8 + 2tg)
    #pragma unroll
    for (int mi = 0; mi < 2; mi++) {
        const int r0 = wm * 32 + mi * 16 + g;
        #pragma unroll
        for (int ni = 0; ni < 4; ni++) {
            const int h = half * 32 + (w1 * 4 + ni) * 4 + tg;
            if (e0 + r0 < NE)
                g_e[(size_t)(e0 + r0) * 64 + h] =
                    __floats2half2_rn(acc[mi][ni][0], acc[mi][ni][1]);
            if (e0 + r0 + 8 < NE)
                g_e[(size_t)(e0 + r0 + 8) * 64 + h] =
                    __floats2half2_rn(acc[mi][ni][2], acc[mi][ni][3]);
        }
    }
}

// ---- E2: attention epilogue. Warp = 8 edges (indices pre-loaded); lane = 4 cols. ----
__global__ __launch_bounds__(256) void epilogue_kernel(
    const void* __restrict__ ei_raw)
{
    const int tid  = threadIdx.x;
    const int w    = tid >> 5, lane = tid & 31;
    const int col  = lane * 4;
    const int e0   = blockIdx.x * 64 + w * 8;
    const bool full = (e0 + 8 <= NE);
    const int idx64 = g_idx64;

    int srcs[8], dsts[8];
    if (idx64) {
        const long long* p = (const long long*)ei_raw;
        #pragma unroll
        for (int ii = 0; ii < 8; ii++) {
            const int eg = e0 + ii;
            const bool v = full || (eg < NE);
            srcs[ii] = v ? (int)__ldg(p + eg) : 0;
            dsts[ii] = v ? (int)__ldg(p + NE + eg) : 0;
        }
    } else {
        const int* p = (const int*)ei_raw;
        #pragma unroll
        for (int ii = 0; ii < 8; ii++) {
            const int eg = e0 + ii;
            const bool v = full || (eg < NE);
            srcs[ii] = v ? __ldg(p + eg) : 0;
            dsts[ii] = v ? __ldg(p + NE + eg) : 0;
        }
    }

    #pragma unroll
    for (int ii = 0; ii < 8; ii++) {
        const int eg = e0 + ii;
        if (full || eg < NE) {
            const int src = srcs[ii], dst = dsts[ii];
            const uint2 eraw = __ldg((const uint2*)(g_e  + (size_t)eg  * 64) + lane);
            const uint2 qraw = __ldg((const uint2*)(g_qh + (size_t)dst * 64) + lane);
            const uint2 kraw = __ldg((const uint2*)(g_kh + (size_t)src * 64) + lane);
            const uint2 vraw = __ldg((const uint2*)(g_vh + (size_t)src * 64) + lane);
            const float2 e01 = __half22float2(*(const __half2*)&eraw.x);
            const float2 e23 = __half22float2(*(const __half2*)&eraw.y);
            const float2 q01 = __half22float2(*(const __half2*)&qraw.x);
            const float2 q23 = __half22float2(*(const __half2*)&qraw.y);
            float2 k01 = __half22float2(*(const __half2*)&kraw.x);
            float2 k23 = __half22float2(*(const __half2*)&kraw.y);
            float2 v01 = __half22float2(*(const __half2*)&vraw.x);
            float2 v23 = __half22float2(*(const __half2*)&vraw.y);
            k01.x += e01.x; k01.y += e01.y; k23.x += e23.x; k23.y += e23.y;
            v01.x += e01.x; v01.y += e01.y; v23.x += e23.x; v23.y += e23.y;

            float p = q01.x * k01.x + q01.y * k01.y + q23.x * k23.x + q23.y * k23.y;
            p += __shfl_xor_sync(0xffffffffu, p, 1);
            p += __shfl_xor_sync(0xffffffffu, p, 2);
            p += __shfl_xor_sync(0xffffffffu, p, 4);
            p += __shfl_xor_sync(0xffffffffu, p, 8);
            const float ex = expf(p * 0.125f);   // 1/sqrt(64); exact softmax w/o max-sub

            red_v4(g_agg + (size_t)dst * D + col,
                   ex * v01.x, ex * v01.y, ex * v23.x, ex * v23.y);
            if ((lane & 15) == 0)
                red_1(&g_sum[dst * 2 + (lane >> 4)], ex);
        }
    }
}

__global__ void finalize_kernel(float* __restrict__ out) {
    int idx = blockIdx.x * blockDim.x + threadIdx.x;
    if (idx >= NN * 32) return;
    const int n = idx >> 5;
    const int h = (idx & 31) >> 4;
    const float inv = 1.0f / (g_sum[n * 2 + h] + 1e-16f);
    float4 a = ((const float4*)g_agg)[idx];
    float4 o = ((float4*)out)[idx];
    o.x += a.x * inv; o.y += a.y * inv; o.z += a.z * inv; o.w += a.w * inv;
    ((float4*)out)[idx] = o;
}

extern "C" void kernel_launch(void* const* d_in, const int* in_sizes, int n_in,
                              void* d_out, int out_size) {
    const float* x           = (const float*)d_in[0];
    const float* last_update = (const float*)d_in[1];
    const void*  ei          = d_in[2];
    const float* t           = (const float*)d_in[3];
    const float* msg         = (const float*)d_in[4];
    const float* time_w      = (const float*)d_in[5];
    const float* time_b      = (const float*)d_in[6];
    const float* Wq          = (const float*)d_in[7];
    const float* bq          = (const float*)d_in[8];
    const float* Wk          = (const float*)d_in[9];
    const float* bk          = (const float*)d_in[10];
    const float* Wv          = (const float*)d_in[11];
    const float* bv          = (const float*)d_in[12];
    const float* We          = (const float*)d_in[13];
    const float* Ws          = (const float*)d_in[14];
    const float* bs          = (const float*)d_in[15];
    float* out = (float*)d_out;

    const int smem_e1 = TE * SAH * 2;     // 21,504 bytes
    const int smem_px = 128 * SXH * 2;    // 34,816 bytes
    static int configured = 0;
    if (!configured) {
        cudaFuncSetAttribute(egemm_kernel,
                             cudaFuncAttributeMaxDynamicSharedMemorySize, smem_e1);
        cudaFuncSetAttribute(proj_kernel,
                             cudaFuncAttributeMaxDynamicSharedMemorySize, smem_px);
        configured = 1;
    }

    prep_kernel<<<(4 * 64 * D + 255) / 256, 256>>>((const long long*)ei, We,
                                                   Wq, Wk, Wv, Ws);
    zero_kernel<<<592, 256>>>();
    proj_kernel<<<dim3((NN + 127) / 128, 4), 256, smem_px>>>(x, bq, bk, bv, bs, out);
    egemm_kernel<<<(NE + TE - 1) / TE, 256, smem_e1>>>(ei, last_update, t, msg,
                                                       time_w, time_b);
    epilogue_kernel<<<(NE + 63) / 64, 256>>>(ei);
    finalize_kernel<<<(NN * 32 + 255) / 256, 256>>>(out);
}

// round 11
// speedup vs baseline: 1.8355x; 1.1248x over previous
#include <cuda_runtime.h>
#include <cuda_fp16.h>

#define NN 50000
#define NE 500000
#define D 128
#define TDIM 32
#define EDIM 160
#define TE 64         // edges per block (edge kernel)
#define SAH 168       // attr tile smem stride (halves)
#define SEH 68        // e-result smem stride (half2)
#define SXH 136       // x tile smem stride (halves)

// ---- scratch (no cudaMalloc allowed) ----
__device__ __half2 g_qh[NN * 64];
__device__ __half2 g_kh[NN * 64];
__device__ __half2 g_vh[NN * 64];
__device__ float   g_agg[NN * D];
__device__ float   g_sum[NN * 2];
__device__ __half2 g_we_h2[80 * D];          // pre-swizzled fp16 We (k-pairs)
__device__ __half2 g_w_h2[4 * 64 * D];       // pre-swizzled fp16 Wq|Wk|Wv|Wskip
__device__ int     g_idx64;

// ---- helpers ----
__device__ __forceinline__ void red_v4(float* p, float a, float b, float c, float d) {
    asm volatile("red.global.add.v4.f32 [%0], {%1,%2,%3,%4};"
                 :: "l"(p), "f"(a), "f"(b), "f"(c), "f"(d) : "memory");
}
__device__ __forceinline__ void red_1(float* p, float a) {
    asm volatile("red.global.add.f32 [%0], %1;" :: "l"(p), "f"(a) : "memory");
}
__device__ __forceinline__ void mma_f16(float* c, const unsigned* a,
                                        unsigned b0, unsigned b1) {
    asm volatile(
        "mma.sync.aligned.m16n8k16.row.col.f32.f16.f16.f32 "
        "{%0,%1,%2,%3}, {%4,%5,%6,%7}, {%8,%9}, {%0,%1,%2,%3};"
        : "+f"(c[0]), "+f"(c[1]), "+f"(c[2]), "+f"(c[3])
        : "r"(a[0]), "r"(a[1]), "r"(a[2]), "r"(a[3]), "r"(b0), "r"(b1));
}

// ---- prep: detect idx width + pre-swizzle weights + zero agg/sum (one launch) ----
__global__ void prep_kernel(const long long* __restrict__ ei,
                            const float* __restrict__ We,
                            const float* __restrict__ Wq,
                            const float* __restrict__ Wk,
                            const float* __restrict__ Wv,
                            const float* __restrict__ Ws) {
    const int i = blockIdx.x * blockDim.x + threadIdx.x;
    const int stride = gridDim.x * blockDim.x;
    if (i == 0) {
        bool ok = true;
        #pragma unroll
        for (int j = 0; j < 16; j++) {
            long long v = ei[j];
            if (v < 0 || v >= NN) ok = false;
        }
        g_idx64 = ok ? 1 : 0;
    }
    if (i < 80 * D) {                     // We: 80 k-pairs x 128 cols
        const int p = i >> 7, c = i & 127;
        const int s = (c >> 6) * 64 + (c & 7) * 8 + ((c >> 3) & 7);
        g_we_h2[p * D + s] = __floats2half2_rn(__ldg(We + (2 * p) * D + c),
                                               __ldg(We + (2 * p + 1) * D + c));
    }
    if (i < 4 * 64 * D) {                 // Wq|Wk|Wv|Ws: 64 k-pairs each
        const int mat = i >> 13, rem = i & 8191;
        const int p = rem >> 7, c = rem & 127;
        const int s = (c >> 6) * 64 + (c & 7) * 8 + ((c >> 3) & 7);
        const float* W = (mat == 0) ? Wq : (mat == 1) ? Wk : (mat == 2) ? Wv : Ws;
        g_w_h2[mat * 64 * D + p * D + s] =
            __floats2half2_rn(__ldg(W + (2 * p) * D + c), __ldg(W + (2 * p + 1) * D + c));
    }
    const float4 z = make_float4(0, 0, 0, 0);
    for (int j = i; j < NN * 32; j += stride) ((float4*)g_agg)[j] = z;
    for (int j = i; j < NN / 2;  j += stride) ((float4*)g_sum)[j] = z;
}

// ---- proj (fp16 mma): q,k,v,skip = x @ W + b. grid = (nodeTiles, 4 mats) ----
__global__ __launch_bounds__(256, 2) void proj_kernel(
    const float* __restrict__ x,
    const float* __restrict__ bq, const float* __restrict__ bk,
    const float* __restrict__ bv, const float* __restrict__ bs,
    float* __restrict__ out)
{
    extern __shared__ __half sX[];   // [128][SXH] fp16 x tile (34.8KB)
    const int tid = threadIdx.x;
    const int n0  = blockIdx.x * 128;
    const int mat = blockIdx.y;

    for (int i = tid; i < 128 * 32; i += 256) {
        const int n = i >> 5, q = i & 31;
        float4 m = make_float4(0, 0, 0, 0);
        if (n0 + n < NN) m = __ldg((const float4*)(x + (size_t)(n0 + n) * D) + q);
        __half2* p = (__half2*)(sX + n * SXH + 4 * q);
        p[0] = __floats2half2_rn(m.x, m.y);
        p[1] = __floats2half2_rn(m.z, m.w);
    }
    __syncthreads();

    const int wid = tid >> 5, lane = tid & 31;
    const int g = lane >> 2, tg = lane & 3;
    const int wm = wid & 3, wn = wid >> 2;

    float acc[2][8][4];
    #pragma unroll
    for (int mi = 0; mi < 2; mi++)
        #pragma unroll
        for (int ni = 0; ni < 8; ni++)
            #pragma unroll
            for (int r = 0; r < 4; r++) acc[mi][ni][r] = 0.f;

    const __half*  Abase = sX + (wm * 32 + g) * SXH + 2 * tg;
    const __half2* Bb    = g_w_h2 + mat * 64 * D + wn * 64 + g * 8;

    #pragma unroll
    for (int ks = 0; ks < 8; ks++) {             // 8 k16-steps, K=128
        const int k0 = ks * 16;
        unsigned a[2][4];
        #pragma unroll
        for (int mi = 0; mi < 2; mi++) {
            const __half* ap = Abase + mi * 16 * SXH + k0;
            a[mi][0] = *(const unsigned*)(ap);
            a[mi][1] = *(const unsigned*)(ap + 8 * SXH);
            a[mi][2] = *(const unsigned*)(ap + 8);
            a[mi][3] = *(const unsigned*)(ap + 8 * SXH + 8);
        }
        const uint4* bp0 = (const uint4*)(Bb + (size_t)(ks * 8 + tg) * D);
        const uint4* bp1 = (const uint4*)(Bb + (size_t)(ks * 8 + tg + 4) * D);
        const uint4 u0 = __ldg(bp0), u1 = __ldg(bp0 + 1);
        const uint4 v0 = __ldg(bp1), v1 = __ldg(bp1 + 1);
        const unsigned b0[8] = {u0.x, u0.y, u0.z, u0.w, u1.x, u1.y, u1.z, u1.w};
        const unsigned b1[8] = {v0.x, v0.y, v0.z, v0.w, v1.x, v1.y, v1.z, v1.w};
        #pragma unroll
        for (int ni = 0; ni < 8; ni++) {
            mma_f16(acc[0][ni], a[0], b0[ni], b1[ni]);
            mma_f16(acc[1][ni], a[1], b0[ni], b1[ni]);
        }
    }

    const float* bias = (mat == 0) ? bq : (mat == 1) ? bk : (mat == 2) ? bv : bs;

    #pragma unroll
    for (int mi = 0; mi < 2; mi++) {
        const int r0 = n0 + wm * 32 + mi * 16 + g;
        #pragma unroll
        for (int ni = 0; ni < 8; ni++) {
            const int c = wn * 64 + ni * 8 + 2 * tg;
            const float2 bb = __ldg((const float2*)(bias + c));
            if (mat == 3) {
                if (r0 < NN)
                    *(float2*)(out + (size_t)r0 * D + c) =
                        make_float2(acc[mi][ni][0] + bb.x, acc[mi][ni][1] + bb.y);
                if (r0 + 8 < NN)
                    *(float2*)(out + (size_t)(r0 + 8) * D + c) =
                        make_float2(acc[mi][ni][2] + bb.x, acc[mi][ni][3] + bb.y);
            } else {
                __half2* dst = (mat == 0) ? g_qh : (mat == 1) ? g_kh : g_vh;
                const int hc = c >> 1;
                if (r0 < NN)
                    dst[(size_t)r0 * 64 + hc] =
                        __floats2half2_rn(acc[mi][ni][0] + bb.x, acc[mi][ni][1] + bb.y);
                if (r0 + 8 < NN)
                    dst[(size_t)(r0 + 8) * 64 + hc] =
                        __floats2half2_rn(acc[mi][ni][2] + bb.x, acc[mi][ni][3] + bb.y);
            }
        }
    }
}

// ---- edge (fused): attr build + fp16 GEMM + attention epilogue. 4 CTAs/SM ----
__global__ __launch_bounds__(256, 4) void edge_kernel(
    const void*  __restrict__ ei_raw,
    const float* __restrict__ last_update,
    const float* __restrict__ t,
    const float* __restrict__ msg,
    const float* __restrict__ time_w,
    const float* __restrict__ time_b)
{
    extern __shared__ __half sA[];      // [TE][SAH] fp16 attr tile (21.5KB)
    __half2* eS = (__half2*)sA;         // [TE][SEH] fp16 e-result, overlays sA
    __shared__ int   s_src[TE], s_dst[TE];
    __shared__ float s_rel[TE];

    const int tid = threadIdx.x;
    const int e0  = blockIdx.x * TE;

    // phase 1: indices + rel time
    if (tid < TE) {
        const int eg = e0 + tid;
        int src = 0, dst = 0; float rel = 0.f;
        if (eg < NE) {
            if (g_idx64) {
                const long long* p = (const long long*)ei_raw;
                src = (int)__ldg(p + eg); dst = (int)__ldg(p + NE + eg);
            } else {
                const int* p = (const int*)ei_raw;
                src = __ldg(p + eg); dst = __ldg(p + NE + eg);
            }
            rel = __ldg(last_update + src) - __ldg(t + eg);
        }
        s_src[tid] = src; s_dst[tid] = dst; s_rel[tid] = rel;
    }
    __syncthreads();

    // phase 2: build attr tile (fp16)
    for (int i = tid; i < TE * TDIM; i += 256) {          // time-encode cols [0,32)
        const int e = i >> 5, k = i & 31;
        float v = 0.f;
        if (e0 + e < NE)
            v = cosf(s_rel[e] * __ldg(time_w + k) + __ldg(time_b + k));
        sA[e * SAH + k] = __float2half(v);
    }
    for (int i = tid; i < TE * 32; i += 256) {            // msg cols [32,160)
        const int e = i >> 5, q = i & 31;
        float4 m = make_float4(0, 0, 0, 0);
        if (e0 + e < NE) m = __ldg((const float4*)(msg + (size_t)(e0 + e) * D) + q);
        __half2* p = (__half2*)(sA + e * SAH + TDIM + 4 * q);
        p[0] = __floats2half2_rn(m.x, m.y);
        p[1] = __floats2half2_rn(m.z, m.w);
    }
    __syncthreads();

    // phase 3: GEMM. 8 warps = 2(M) x 4(N); warp tile 32x32.
    const int wid = tid >> 5, lane = tid & 31;
    const int g = lane >> 2, tg = lane & 3;
    const int wm = wid & 1, wn = wid >> 1;
    const int half = wn >> 1, w1 = wn & 1;

    float acc[2][4][4];
    #pragma unroll
    for (int mi = 0; mi < 2; mi++)
        #pragma unroll
        for (int ni = 0; ni < 4; ni++)
            #pragma unroll
            for (int r = 0; r < 4; r++) acc[mi][ni][r] = 0.f;

    const __half*  Abase = sA + (wm * 32 + g) * SAH + 2 * tg;
    const __half2* Bb    = g_we_h2 + half * 64 + g * 8 + w1 * 4;

    #pragma unroll
    for (int ks = 0; ks < 10; ks++) {             // 10 k16-steps, K=160
        const int k0 = ks * 16;
        unsigned a[2][4];
        #pragma unroll
        for (int mi = 0; mi < 2; mi++) {
            const __half* ap = Abase + mi * 16 * SAH + k0;
            a[mi][0] = *(const unsigned*)(ap);
            a[mi][1] = *(const unsigned*)(ap + 8 * SAH);
            a[mi][2] = *(const unsigned*)(ap + 8);
            a[mi][3] = *(const unsigned*)(ap + 8 * SAH + 8);
        }
        const uint4 u = __ldg((const uint4*)(Bb + (size_t)(ks * 8 + tg) * D));
        const uint4 v = __ldg((const uint4*)(Bb + (size_t)(ks * 8 + tg + 4) * D));
        const unsigned b0[4] = {u.x, u.y, u.z, u.w};
        const unsigned b1[4] = {v.x, v.y, v.z, v.w};
        #pragma unroll
        for (int ni = 0; ni < 4; ni++) {
            mma_f16(acc[0][ni], a[0], b0[ni], b1[ni]);
            mma_f16(acc[1][ni], a[1], b0[ni], b1[ni]);
        }
    }
    __syncthreads();   // all warps done reading sA

    // phase 4: accumulators -> smem as fp16 (same col map validated in R8-R10)
    #pragma unroll
    for (int mi = 0; mi < 2; mi++) {
        const int r0 = wm * 32 + mi * 16 + g;
        #pragma unroll
        for (int ni = 0; ni < 4; ni++) {
            const int h = half * 32 + (w1 * 4 + ni) * 4 + tg;
            eS[r0 * SEH + h]       = __floats2half2_rn(acc[mi][ni][0], acc[mi][ni][1]);
            eS[(r0 + 8) * SEH + h] = __floats2half2_rn(acc[mi][ni][2], acc[mi][ni][3]);
        }
    }
    __syncthreads();

    // phase 5: attention epilogue. Warp = 8 edges; lane = 4 cols.
    const int col = lane * 4;
    #pragma unroll
    for (int ii = 0; ii < 8; ii++) {
        const int eL = wid * 8 + ii;
        const int eg = e0 + eL;
        if (eg < NE) {
            const int src = s_src[eL], dst = s_dst[eL];
            const uint2 eraw = *(const uint2*)(eS + eL * SEH + 2 * lane);
            const uint2 qraw = __ldg((const uint2*)(g_qh + (size_t)dst * 64) + lane);
            const uint2 kraw = __ldg((const uint2*)(g_kh + (size_t)src * 64) + lane);
            const uint2 vraw = __ldg((const uint2*)(g_vh + (size_t)src * 64) + lane);
            const float2 e01 = __half22float2(*(const __half2*)&eraw.x);
            const float2 e23 = __half22float2(*(const __half2*)&eraw.y);
            const float2 q01 = __half22float2(*(const __half2*)&qraw.x);
            const float2 q23 = __half22float2(*(const __half2*)&qraw.y);
            float2 k01 = __half22float2(*(const __half2*)&kraw.x);
            float2 k23 = __half22float2(*(const __half2*)&kraw.y);
            float2 v01 = __half22float2(*(const __half2*)&vraw.x);
            float2 v23 = __half22float2(*(const __half2*)&vraw.y);
            k01.x += e01.x; k01.y += e01.y; k23.x += e23.x; k23.y += e23.y;
            v01.x += e01.x; v01.y += e01.y; v23.x += e23.x; v23.y += e23.y;

            float p = q01.x * k01.x + q01.y * k01.y + q23.x * k23.x + q23.y * k23.y;
            p += __shfl_xor_sync(0xffffffffu, p, 1);
            p += __shfl_xor_sync(0xffffffffu, p, 2);
            p += __shfl_xor_sync(0xffffffffu, p, 4);
            p += __shfl_xor_sync(0xffffffffu, p, 8);
            const float ex = expf(p * 0.125f);   // 1/sqrt(64); exact softmax w/o max-sub

            red_v4(g_agg + (size_t)dst * D + col,
                   ex * v01.x, ex * v01.y, ex * v23.x, ex * v23.y);
            if ((lane & 15) == 0)
                red_1(&g_sum[dst * 2 + (lane >> 4)], ex);
        }
    }
}

__global__ void finalize_kernel(float* __restrict__ out) {
    int idx = blockIdx.x * blockDim.x + threadIdx.x;
    if (idx >= NN * 32) return;
    const int n = idx >> 5;
    const int h = (idx & 31) >> 4;
    const float inv = 1.0f / (g_sum[n * 2 + h] + 1e-16f);
    float4 a = ((const float4*)g_agg)[idx];
    float4 o = ((float4*)out)[idx];
    o.x += a.x * inv; o.y += a.y * inv; o.z += a.z * inv; o.w += a.w * inv;
    ((float4*)out)[idx] = o;
}

extern "C" void kernel_launch(void* const* d_in, const int* in_sizes, int n_in,
                              void* d_out, int out_size) {
    const float* x           = (const float*)d_in[0];
    const float* last_update = (const float*)d_in[1];
    const void*  ei          = d_in[2];
    const float* t           = (const float*)d_in[3];
    const float* msg         = (const float*)d_in[4];
    const float* time_w      = (const float*)d_in[5];
    const float* time_b      = (const float*)d_in[6];
    const float* Wq          = (const float*)d_in[7];
    const float* bq          = (const float*)d_in[8];
    const float* Wk          = (const float*)d_in[9];
    const float* bk          = (const float*)d_in[10];
    const float* Wv          = (const float*)d_in[11];
    const float* bv          = (const float*)d_in[12];
    const float* We          = (const float*)d_in[13];
    const float* Ws          = (const float*)d_in[14];
    const float* bs          = (const float*)d_in[15];
    float* out = (float*)d_out;

    const int smem_e1 = TE * SAH * 2;     // 21,504 bytes
    const int smem_px = 128 * SXH * 2;    // 34,816 bytes
    static int configured = 0;
    if (!configured) {
        cudaFuncSetAttribute(edge_kernel,
                             cudaFuncAttributeMaxDynamicSharedMemorySize, smem_e1);
        cudaFuncSetAttribute(proj_kernel,
                             cudaFuncAttributeMaxDynamicSharedMemorySize, smem_px);
        configured = 1;
    }

    prep_kernel<<<592, 256>>>((const long long*)ei, We, Wq, Wk, Wv, Ws);
    proj_kernel<<<dim3((NN + 127) / 128, 4), 256, smem_px>>>(x, bq, bk, bv, bs, out);
    edge_kernel<<<(NE + TE - 1) / TE, 256, smem_e1>>>(ei, last_update, t, msg,
                                                      time_w, time_b);
    finalize_kernel<<<(NN * 32 + 255) / 256, 256>>>(out);
}

// round 12
// speedup vs baseline: 1.9032x; 1.0369x over previous
#include <cuda_runtime.h>
#include <cuda_fp16.h>

#define NN 50000
#define NE 500000
#define D 128
#define TDIM 32
#define EDIM 160
#define TE 64         // edges per block (edge kernel)
#define SAH 168       // attr tile smem stride (halves)
#define SEH 68        // e-result smem stride (half2)
#define SXH 136       // x tile smem stride (halves)

// ---- scratch (no cudaMalloc allowed) ----
__device__ __half2 g_qh[NN * 64];
__device__ __half2 g_kh[NN * 64];
__device__ __half2 g_vh[NN * 64];
__device__ float   g_agg[NN * D];
__device__ float   g_sum[NN * 2];
__device__ __half2 g_we_h2[80 * D];          // pre-swizzled fp16 We (k-pairs)
__device__ __half2 g_w_h2[4 * 64 * D];       // pre-swizzled fp16 Wq|Wk|Wv|Wskip
__device__ int     g_idx64;

// ---- helpers ----
__device__ __forceinline__ void red_v4(float* p, float a, float b, float c, float d) {
    asm volatile("red.global.add.v4.f32 [%0], {%1,%2,%3,%4};"
                 :: "l"(p), "f"(a), "f"(b), "f"(c), "f"(d) : "memory");
}
__device__ __forceinline__ void red_1(float* p, float a) {
    asm volatile("red.global.add.f32 [%0], %1;" :: "l"(p), "f"(a) : "memory");
}
__device__ __forceinline__ void mma_f16(float* c, const unsigned* a,
                                        unsigned b0, unsigned b1) {
    asm volatile(
        "mma.sync.aligned.m16n8k16.row.col.f32.f16.f16.f32 "
        "{%0,%1,%2,%3}, {%4,%5,%6,%7}, {%8,%9}, {%0,%1,%2,%3};"
        : "+f"(c[0]), "+f"(c[1]), "+f"(c[2]), "+f"(c[3])
        : "r"(a[0]), "r"(a[1]), "r"(a[2]), "r"(a[3]), "r"(b0), "r"(b1));
}

// ---- prep: detect idx width + pre-swizzle weights + zero agg/sum (one launch) ----
__global__ void prep_kernel(const long long* __restrict__ ei,
                            const float* __restrict__ We,
                            const float* __restrict__ Wq,
                            const float* __restrict__ Wk,
                            const float* __restrict__ Wv,
                            const float* __restrict__ Ws) {
    const int i = blockIdx.x * blockDim.x + threadIdx.x;
    const int stride = gridDim.x * blockDim.x;
    if (i == 0) {
        bool ok = true;
        #pragma unroll
        for (int j = 0; j < 16; j++) {
            long long v = ei[j];
            if (v < 0 || v >= NN) ok = false;
        }
        g_idx64 = ok ? 1 : 0;
    }
    if (i < 80 * D) {                     // We: 80 k-pairs x 128 cols
        const int p = i >> 7, c = i & 127;
        const int s = (c >> 6) * 64 + (c & 7) * 8 + ((c >> 3) & 7);
        g_we_h2[p * D + s] = __floats2half2_rn(__ldg(We + (2 * p) * D + c),
                                               __ldg(We + (2 * p + 1) * D + c));
    }
    if (i < 4 * 64 * D) {                 // Wq|Wk|Wv|Ws: 64 k-pairs each
        const int mat = i >> 13, rem = i & 8191;
        const int p = rem >> 7, c = rem & 127;
        const int s = (c >> 6) * 64 + (c & 7) * 8 + ((c >> 3) & 7);
        const float* W = (mat == 0) ? Wq : (mat == 1) ? Wk : (mat == 2) ? Wv : Ws;
        g_w_h2[mat * 64 * D + p * D + s] =
            __floats2half2_rn(__ldg(W + (2 * p) * D + c), __ldg(W + (2 * p + 1) * D + c));
    }
    const float4 z = make_float4(0, 0, 0, 0);
    for (int j = i; j < NN * 32; j += stride) ((float4*)g_agg)[j] = z;
    for (int j = i; j < NN / 2;  j += stride) ((float4*)g_sum)[j] = z;
}

// ---- proj (fp16 mma): q,k,v,skip = x @ W + b. grid = (nodeTiles, 4 mats) ----
__global__ __launch_bounds__(256, 2) void proj_kernel(
    const float* __restrict__ x,
    const float* __restrict__ bq, const float* __restrict__ bk,
    const float* __restrict__ bv, const float* __restrict__ bs,
    float* __restrict__ out)
{
    extern __shared__ __half sX[];   // [128][SXH] fp16 x tile (34.8KB)
    const int tid = threadIdx.x;
    const int n0  = blockIdx.x * 128;
    const int mat = blockIdx.y;

    for (int i = tid; i < 128 * 32; i += 256) {
        const int n = i >> 5, q = i & 31;
        float4 m = make_float4(0, 0, 0, 0);
        if (n0 + n < NN) m = __ldg((const float4*)(x + (size_t)(n0 + n) * D) + q);
        __half2* p = (__half2*)(sX + n * SXH + 4 * q);
        p[0] = __floats2half2_rn(m.x, m.y);
        p[1] = __floats2half2_rn(m.z, m.w);
    }
    __syncthreads();

    const int wid = tid >> 5, lane = tid & 31;
    const int g = lane >> 2, tg = lane & 3;
    const int wm = wid & 3, wn = wid >> 2;

    float acc[2][8][4];
    #pragma unroll
    for (int mi = 0; mi < 2; mi++)
        #pragma unroll
        for (int ni = 0; ni < 8; ni++)
            #pragma unroll
            for (int r = 0; r < 4; r++) acc[mi][ni][r] = 0.f;

    const __half*  Abase = sX + (wm * 32 + g) * SXH + 2 * tg;
    const __half2* Bb    = g_w_h2 + mat * 64 * D + wn * 64 + g * 8;

    #pragma unroll
    for (int ks = 0; ks < 8; ks++) {             // 8 k16-steps, K=128
        const int k0 = ks * 16;
        unsigned a[2][4];
        #pragma unroll
        for (int mi = 0; mi < 2; mi++) {
            const __half* ap = Abase + mi * 16 * SXH + k0;
            a[mi][0] = *(const unsigned*)(ap);
            a[mi][1] = *(const unsigned*)(ap + 8 * SXH);
            a[mi][2] = *(const unsigned*)(ap + 8);
            a[mi][3] = *(const unsigned*)(ap + 8 * SXH + 8);
        }
        const uint4* bp0 = (const uint4*)(Bb + (size_t)(ks * 8 + tg) * D);
        const uint4* bp1 = (const uint4*)(Bb + (size_t)(ks * 8 + tg + 4) * D);
        const uint4 u0 = __ldg(bp0), u1 = __ldg(bp0 + 1);
        const uint4 v0 = __ldg(bp1), v1 = __ldg(bp1 + 1);
        const unsigned b0[8] = {u0.x, u0.y, u0.z, u0.w, u1.x, u1.y, u1.z, u1.w};
        const unsigned b1[8] = {v0.x, v0.y, v0.z, v0.w, v1.x, v1.y, v1.z, v1.w};
        #pragma unroll
        for (int ni = 0; ni < 8; ni++) {
            mma_f16(acc[0][ni], a[0], b0[ni], b1[ni]);
            mma_f16(acc[1][ni], a[1], b0[ni], b1[ni]);
        }
    }

    const float* bias = (mat == 0) ? bq : (mat == 1) ? bk : (mat == 2) ? bv : bs;

    #pragma unroll
    for (int mi = 0; mi < 2; mi++) {
        const int r0 = n0 + wm * 32 + mi * 16 + g;
        #pragma unroll
        for (int ni = 0; ni < 8; ni++) {
            const int c = wn * 64 + ni * 8 + 2 * tg;
            const float2 bb = __ldg((const float2*)(bias + c));
            if (mat == 3) {
                if (r0 < NN)
                    *(float2*)(out + (size_t)r0 * D + c) =
                        make_float2(acc[mi][ni][0] + bb.x, acc[mi][ni][1] + bb.y);
                if (r0 + 8 < NN)
                    *(float2*)(out + (size_t)(r0 + 8) * D + c) =
                        make_float2(acc[mi][ni][2] + bb.x, acc[mi][ni][3] + bb.y);
            } else {
                __half2* dst = (mat == 0) ? g_qh : (mat == 1) ? g_kh : g_vh;
                const int hc = c >> 1;
                if (r0 < NN)
                    dst[(size_t)r0 * 64 + hc] =
                        __floats2half2_rn(acc[mi][ni][0] + bb.x, acc[mi][ni][1] + bb.y);
                if (r0 + 8 < NN)
                    dst[(size_t)(r0 + 8) * 64 + hc] =
                        __floats2half2_rn(acc[mi][ni][2] + bb.x, acc[mi][ni][3] + bb.y);
            }
        }
    }
}

// ---- edge (fused): attr build + fp16 GEMM + attention epilogue. 4 CTAs/SM ----
__global__ __launch_bounds__(256, 4) void edge_kernel(
    const void*  __restrict__ ei_raw,
    const float* __restrict__ last_update,
    const float* __restrict__ t,
    const float* __restrict__ msg,
    const float* __restrict__ time_w,
    const float* __restrict__ time_b)
{
    extern __shared__ __half sA[];      // [TE][SAH] fp16 attr tile (21.5KB)
    __half2* eS = (__half2*)sA;         // [TE][SEH] fp16 e-result, overlays sA
    __shared__ int   s_src[TE], s_dst[TE];
    __shared__ float s_rel[TE];

    const int tid = threadIdx.x;
    const int e0  = blockIdx.x * TE;

    // phase 1: indices + rel time
    if (tid < TE) {
        const int eg = e0 + tid;
        int src = 0, dst = 0; float rel = 0.f;
        if (eg < NE) {
            if (g_idx64) {
                const long long* p = (const long long*)ei_raw;
                src = (int)__ldg(p + eg); dst = (int)__ldg(p + NE + eg);
            } else {
                const int* p = (const int*)ei_raw;
                src = __ldg(p + eg); dst = __ldg(p + NE + eg);
            }
            rel = __ldg(last_update + src) - __ldg(t + eg);
        }
        s_src[tid] = src; s_dst[tid] = dst; s_rel[tid] = rel;
    }
    __syncthreads();

    // phase 2: build attr tile (fp16). Fast cos: RRO+MUFU (abs err ~|x|*2^-22
    // ~ 6e-5 rad << fp16 quantization 5e-4 of the stored value).
    {
        const int k = tid & 31;                         // thread's fixed time-dim
        const float tw = __ldg(time_w + k);
        const float tb = __ldg(time_b + k);
        #pragma unroll
        for (int j = 0; j < TE * TDIM / 256; j++) {     // 8 iters, e = (tid>>5)+8j
            const int e = (tid >> 5) + j * 8;
            float v = 0.f;
            if (e0 + e < NE) v = __cosf(fmaf(s_rel[e], tw, tb));
            sA[e * SAH + k] = __float2half(v);
        }
    }
    for (int i = tid; i < TE * 32; i += 256) {          // msg cols [32,160)
        const int e = i >> 5, q = i & 31;
        float4 m = make_float4(0, 0, 0, 0);
        if (e0 + e < NE) m = __ldg((const float4*)(msg + (size_t)(e0 + e) * D) + q);
        __half2* p = (__half2*)(sA + e * SAH + TDIM + 4 * q);
        p[0] = __floats2half2_rn(m.x, m.y);
        p[1] = __floats2half2_rn(m.z, m.w);
    }
    __syncthreads();

    // phase 3: GEMM. 8 warps = 2(M) x 4(N); warp tile 32x32.
    const int wid = tid >> 5, lane = tid & 31;
    const int g = lane >> 2, tg = lane & 3;
    const int wm = wid & 1, wn = wid >> 1;
    const int half = wn >> 1, w1 = wn & 1;

    float acc[2][4][4];
    #pragma unroll
    for (int mi = 0; mi < 2; mi++)
        #pragma unroll
        for (int ni = 0; ni < 4; ni++)
            #pragma unroll
            for (int r = 0; r < 4; r++) acc[mi][ni][r] = 0.f;

    const __half*  Abase = sA + (wm * 32 + g) * SAH + 2 * tg;
    const __half2* Bb    = g_we_h2 + half * 64 + g * 8 + w1 * 4;

    #pragma unroll
    for (int ks = 0; ks < 10; ks++) {             // 10 k16-steps, K=160
        const int k0 = ks * 16;
        unsigned a[2][4];
        #pragma unroll
        for (int mi = 0; mi < 2; mi++) {
            const __half* ap = Abase + mi * 16 * SAH + k0;
            a[mi][0] = *(const unsigned*)(ap);
            a[mi][1] = *(const unsigned*)(ap + 8 * SAH);
            a[mi][2] = *(const unsigned*)(ap + 8);
            a[mi][3] = *(const unsigned*)(ap + 8 * SAH + 8);
        }
        const uint4 u = __ldg((const uint4*)(Bb + (size_t)(ks * 8 + tg) * D));
        const uint4 v = __ldg((const uint4*)(Bb + (size_t)(ks * 8 + tg + 4) * D));
        const unsigned b0[4] = {u.x, u.y, u.z, u.w};
        const unsigned b1[4] = {v.x, v.y, v.z, v.w};
        #pragma unroll
        for (int ni = 0; ni < 4; ni++) {
            mma_f16(acc[0][ni], a[0], b0[ni], b1[ni]);
            mma_f16(acc[1][ni], a[1], b0[ni], b1[ni]);
        }
    }
    __syncthreads();   // all warps done reading sA

    // phase 4: accumulators -> smem as fp16
    #pragma unroll
    for (int mi = 0; mi < 2; mi++) {
        const int r0 = wm * 32 + mi * 16 + g;
        #pragma unroll
        for (int ni = 0; ni < 4; ni++) {
            const int h = half * 32 + (w1 * 4 + ni) * 4 + tg;
            eS[r0 * SEH + h]       = __floats2half2_rn(acc[mi][ni][0], acc[mi][ni][1]);
            eS[(r0 + 8) * SEH + h] = __floats2half2_rn(acc[mi][ni][2], acc[mi][ni][3]);
        }
    }
    __syncthreads();

    // phase 5: attention epilogue. Warp = 8 edges; lane = 4 cols.
    const int col = lane * 4;
    #pragma unroll
    for (int ii = 0; ii < 8; ii++) {
        const int eL = wid * 8 + ii;
        const int eg = e0 + eL;
        if (eg < NE) {
            const int src = s_src[eL], dst = s_dst[eL];
            const uint2 eraw = *(const uint2*)(eS + eL * SEH + 2 * lane);
            const uint2 qraw = __ldg((const uint2*)(g_qh + (size_t)dst * 64) + lane);
            const uint2 kraw = __ldg((const uint2*)(g_kh + (size_t)src * 64) + lane);
            const uint2 vraw = __ldg((const uint2*)(g_vh + (size_t)src * 64) + lane);
            const float2 e01 = __half22float2(*(const __half2*)&eraw.x);
            const float2 e23 = __half22float2(*(const __half2*)&eraw.y);
            const float2 q01 = __half22float2(*(const __half2*)&qraw.x);
            const float2 q23 = __half22float2(*(const __half2*)&qraw.y);
            float2 k01 = __half22float2(*(const __half2*)&kraw.x);
            float2 k23 = __half22float2(*(const __half2*)&kraw.y);
            float2 v01 = __half22float2(*(const __half2*)&vraw.x);
            float2 v23 = __half22float2(*(const __half2*)&vraw.y);
            k01.x += e01.x; k01.y += e01.y; k23.x += e23.x; k23.y += e23.y;
            v01.x += e01.x; v01.y += e01.y; v23.x += e23.x; v23.y += e23.y;

            float p = q01.x * k01.x + q01.y * k01.y + q23.x * k23.x + q23.y * k23.y;
            p += __shfl_xor_sync(0xffffffffu, p, 1);
            p += __shfl_xor_sync(0xffffffffu, p, 2);
            p += __shfl_xor_sync(0xffffffffu, p, 4);
            p += __shfl_xor_sync(0xffffffffu, p, 8);
            const float ex = expf(p * 0.125f);   // 1/sqrt(64); exact softmax w/o max-sub

            red_v4(g_agg + (size_t)dst * D + col,
                   ex * v01.x, ex * v01.y, ex * v23.x, ex * v23.y);
            if ((lane & 15) == 0)
                red_1(&g_sum[dst * 2 + (lane >> 4)], ex);
        }
    }
}

__global__ void finalize_kernel(float* __restrict__ out) {
    int idx = blockIdx.x * blockDim.x + threadIdx.x;
    if (idx >= NN * 32) return;
    const int n = idx >> 5;
    const int h = (idx & 31) >> 4;
    const float inv = 1.0f / (g_sum[n * 2 + h] + 1e-16f);
    float4 a = ((const float4*)g_agg)[idx];
    float4 o = ((float4*)out)[idx];
    o.x += a.x * inv; o.y += a.y * inv; o.z += a.z * inv; o.w += a.w * inv;
    ((float4*)out)[idx] = o;
}

extern "C" void kernel_launch(void* const* d_in, const int* in_sizes, int n_in,
                              void* d_out, int out_size) {
    const float* x           = (const float*)d_in[0];
    const float* last_update = (const float*)d_in[1];
    const void*  ei          = d_in[2];
    const float* t           = (const float*)d_in[3];
    const float* msg         = (const float*)d_in[4];
    const float* time_w      = (const float*)d_in[5];
    const float* time_b      = (const float*)d_in[6];
    const float* Wq          = (const float*)d_in[7];
    const float* bq          = (const float*)d_in[8];
    const float* Wk          = (const float*)d_in[9];
    const float* bk          = (const float*)d_in[10];
    const float* Wv          = (const float*)d_in[11];
    const float* bv          = (const float*)d_in[12];
    const float* We          = (const float*)d_in[13];
    const float* Ws          = (const float*)d_in[14];
    const float* bs          = (const float*)d_in[15];
    float* out = (float*)d_out;

    const int smem_e1 = TE * SAH * 2;     // 21,504 bytes
    const int smem_px = 128 * SXH * 2;    // 34,816 bytes
    static int configured = 0;
    if (!configured) {
        cudaFuncSetAttribute(edge_kernel,
                             cudaFuncAttributeMaxDynamicSharedMemorySize, smem_e1);
        cudaFuncSetAttribute(proj_kernel,
                             cudaFuncAttributeMaxDynamicSharedMemorySize, smem_px);
        configured = 1;
    }

    prep_kernel<<<592, 256>>>((const long long*)ei, We, Wq, Wk, Wv, Ws);
    proj_kernel<<<dim3((NN + 127) / 128, 4), 256, smem_px>>>(x, bq, bk, bv, bs, out);
    edge_kernel<<<(NE + TE - 1) / TE, 256, smem_e1>>>(ei, last_update, t, msg,
                                                      time_w, time_b);
    finalize_kernel<<<(NN * 32 + 255) / 256, 256>>>(out);
}